// round 14
// baseline (speedup 1.0000x reference)
#include <cuda_runtime.h>
#include <cuda_bf16.h>
#include <cstdint>
#include <cstddef>

// Problem constants (fixed by the reference)
#define BB 128
#define TT 2048
#define II 32
#define HH 64
constexpr int NROWS  = BB * TT;        // 262144
constexpr int NELEM  = NROWS * HH;     // 16,777,216 per plane
constexpr int NCHAIN = BB * 2 * HH;    // 16384 scan chains
constexpr int CHK    = 8;              // chunks per chain (scan split)
constexpr int CLEN   = TT / CHK;       // 256

// Scratch (device globals — no runtime allocation allowed).
__device__ float g_xw0[NELEM];
__device__ float g_xw1[NELEM];
__device__ float g_h0[NELEM];
__device__ float g_h1[NELEM];
__device__ float g_S  [NCHAIN * CHK];
__device__ float g_hl [NCHAIN * CHK];  // per-chunk local-scan end value
__device__ float g_hin[NCHAIN * CHK];

// Deduped B' image for the MMA MLP: 128 rows x [Whi(128)|Wlo(128)] bf16,
// pitch 264 elems (528 B)
constexpr int BPITCHE = 264;
__device__ uint32_t g_Bimg[128 * BPITCHE / 2];   // 67584 bytes

// B' image for the MMA projection: 128 rows x 104 bf16 (pitch 208 B),
// K = [Whi(32) | Wlo(32) | Whi(32)]
constexpr int PPITCHE = 104;
__device__ uint32_t g_BimgP[128 * PPITCHE / 2];
__device__ float    g_biasP[128];

typedef unsigned long long u64;

__device__ __forceinline__ bool row_is_identity(const float* W, int j) {
    bool ok = true;
#pragma unroll
    for (int k = 0; k < HH; k++) ok &= (W[j * HH + k] == ((k == j) ? 1.0f : 0.0f));
    return ok;
}

__device__ __forceinline__ uint32_t smem_u32(const void* p) {
    uint32_t a;
    asm("{ .reg .u64 t; cvta.to.shared.u64 t, %1; cvt.u32.u64 %0, t; }"
        : "=r"(a) : "l"(p));
    return a;
}

// ============================================================================
// Prep: build both B' images + proj bias vector.
// ============================================================================
__global__ __launch_bounds__(512) void prep_kernel(
    const float* __restrict__ ff0w,
    const float* __restrict__ Wihf, const float* __restrict__ Wihb,
    const float* __restrict__ bihf, const float* __restrict__ bhhf,
    const float* __restrict__ bihb, const float* __restrict__ bhhb)
{
    const int tx = threadIdx.x;
    const int j  = tx >> 2;
    const int kq = tx & 3;

    // MLP image (deduped): [128 j][256 k], pitch 264; K = [Whi | Wlo]
    for (int kp = kq * 32; kp < (kq + 1) * 32; kp++) {
        const int c = 2 * kp;
        const int lo_type = (c >= 128);
        const int sk = lo_type ? (c - 128) : c;
        float w0 = ff0w[j * 128 + sk], w1 = ff0w[j * 128 + sk + 1];
        __nv_bfloat16 h0 = __float2bfloat16(w0), h1 = __float2bfloat16(w1);
        __nv_bfloat16 o0, o1;
        if (lo_type) {
            o0 = __float2bfloat16(w0 - __bfloat162float(h0));
            o1 = __float2bfloat16(w1 - __bfloat162float(h1));
        } else { o0 = h0; o1 = h1; }
        __nv_bfloat162 p2 = make_bfloat162(o0, o1);
        g_Bimg[j * (BPITCHE / 2) + kp] = *reinterpret_cast<uint32_t*>(&p2);
    }

    // proj image: [128 n][96 k], pitch 104; K = [Whi|Wlo|Whi]; n = dir*64+jr
    {
        const int n = j;
        const int dir = n >> 6, jr = n & 63;
        const float* W = dir ? Wihb : Wihf;
        for (int kp = kq * 12; kp < (kq + 1) * 12; kp++) {
            const int c = 2 * kp;
            int sk, lo_type;
            if (c < 32)      { sk = c;      lo_type = 0; }
            else if (c < 64) { sk = c - 32; lo_type = 1; }
            else             { sk = c - 64; lo_type = 0; }
            float w0 = W[jr * II + sk], w1 = W[jr * II + sk + 1];
            __nv_bfloat16 h0 = __float2bfloat16(w0), h1 = __float2bfloat16(w1);
            __nv_bfloat16 o0, o1;
            if (lo_type) {
                o0 = __float2bfloat16(w0 - __bfloat162float(h0));
                o1 = __float2bfloat16(w1 - __bfloat162float(h1));
            } else { o0 = h0; o1 = h1; }
            __nv_bfloat162 p2 = make_bfloat162(o0, o1);
            g_BimgP[n * (PPITCHE / 2) + kp] = *reinterpret_cast<uint32_t*>(&p2);
        }
        if (kq == 0)
            g_biasP[n] = dir ? (bihb[jr] + bhhb[jr]) : (bihf[jr] + bhhf[jr]);
    }
}

// ============================================================================
// Kernel 1: input projection via mma.sync (R13 measured-best, unchanged).
// ============================================================================
constexpr int PAPITCH = 208;
constexpr int PSM_A   = 0;
constexpr int PSM_B   = 128 * PAPITCH;              // 26624
constexpr int PSM_AB  = PSM_B + 128 * PAPITCH;      // 53248
constexpr int PSM_OUT = 128 * 132 * 4;              // 67584
constexpr int PSM_TOT = PSM_OUT > PSM_AB ? PSM_OUT : PSM_AB;

__global__ __launch_bounds__(256, 2)
void proj_mma_kernel(const float* __restrict__ x)
{
    extern __shared__ __align__(128) char smem[];
    __shared__ float sbias[128];

    const int tx   = threadIdx.x;
    const int wid  = tx >> 5;
    const int lane = tx & 31;
    const int row0 = blockIdx.x * 128;
    const int b    = row0 >> 11;            // TT = 2048
    const int t0   = row0 & (TT - 1);

    if (tx < 128) sbias[tx] = g_biasP[tx];

    {
        const float4* src = reinterpret_cast<const float4*>(g_BimgP);
        float4* dst = reinterpret_cast<float4*>(smem + PSM_B);
        for (int i = tx; i < PSM_B / 16; i += 256) dst[i] = src[i];
    }

    {
        const int r = tx >> 1, half = tx & 1;
        const float* px = &x[(size_t)(b * TT + t0 + r) * II];
        float hv[II];
#pragma unroll
        for (int q = 0; q < 8; q++) *(float4*)&hv[q * 4] = *(const float4*)&px[q * 4];
        char* A = smem + PSM_A + r * PAPITCH;
        if (half == 0) {
#pragma unroll
            for (int kq = 0; kq < 8; kq++) {
                const int c = kq * 4;
                __nv_bfloat162 q0 = make_bfloat162(__float2bfloat16(hv[c]),
                                                   __float2bfloat16(hv[c + 1]));
                __nv_bfloat162 q1 = make_bfloat162(__float2bfloat16(hv[c + 2]),
                                                   __float2bfloat16(hv[c + 3]));
                u64 pq = ((u64)(*reinterpret_cast<uint32_t*>(&q1)) << 32)
                       |  (u64)(*reinterpret_cast<uint32_t*>(&q0));
                *(u64*)(A + c * 2) = pq;
            }
        } else {
#pragma unroll
            for (int kq = 0; kq < 8; kq++) {
                const int c = kq * 4;
                __nv_bfloat16 b0 = __float2bfloat16(hv[c]);
                __nv_bfloat16 b1 = __float2bfloat16(hv[c + 1]);
                __nv_bfloat16 b2 = __float2bfloat16(hv[c + 2]);
                __nv_bfloat16 b3 = __float2bfloat16(hv[c + 3]);
                __nv_bfloat162 h01 = make_bfloat162(b0, b1);
                __nv_bfloat162 h23 = make_bfloat162(b2, b3);
                u64 hq = ((u64)(*reinterpret_cast<uint32_t*>(&h23)) << 32)
                       |  (u64)(*reinterpret_cast<uint32_t*>(&h01));
                __nv_bfloat162 l01 = make_bfloat162(
                    __float2bfloat16(hv[c]     - __bfloat162float(b0)),
                    __float2bfloat16(hv[c + 1] - __bfloat162float(b1)));
                __nv_bfloat162 l23 = make_bfloat162(
                    __float2bfloat16(hv[c + 2] - __bfloat162float(b2)),
                    __float2bfloat16(hv[c + 3] - __bfloat162float(b3)));
                u64 lq = ((u64)(*reinterpret_cast<uint32_t*>(&l23)) << 32)
                       |  (u64)(*reinterpret_cast<uint32_t*>(&l01));
                *(u64*)(A + (c + 32) * 2) = hq;
                *(u64*)(A + (c + 64) * 2) = lq;
            }
        }
    }
    __syncthreads();

    const uint32_t aAddr = smem_u32(smem) + PSM_A
        + (uint32_t)(wid * 16 + (lane & 15)) * PAPITCH + (uint32_t)(lane >> 4) * 16;
    const uint32_t bAddr = smem_u32(smem) + PSM_B
        + (uint32_t)(lane & 7) * PAPITCH + (uint32_t)((lane >> 3) & 1) * 16;

    float c[16][4];
#pragma unroll
    for (int nt = 0; nt < 16; nt++)
#pragma unroll
        for (int q = 0; q < 4; q++) c[nt][q] = 0.0f;

#pragma unroll
    for (int kk = 0; kk < 6; kk++) {
        uint32_t a0, a1, a2, a3;
        asm volatile("ldmatrix.sync.aligned.m8n8.x4.shared.b16 {%0,%1,%2,%3}, [%4];"
                     : "=r"(a0), "=r"(a1), "=r"(a2), "=r"(a3)
                     : "r"(aAddr + kk * 32));
#pragma unroll
        for (int nt = 0; nt < 16; nt++) {
            uint32_t b0, b1;
            asm volatile("ldmatrix.sync.aligned.m8n8.x2.shared.b16 {%0,%1}, [%2];"
                         : "=r"(b0), "=r"(b1)
                         : "r"(bAddr + (uint32_t)nt * 8 * PAPITCH + kk * 32));
            asm volatile(
                "mma.sync.aligned.m16n8k16.row.col.f32.bf16.bf16.f32 "
                "{%0,%1,%2,%3}, {%4,%5,%6,%7}, {%8,%9}, {%0,%1,%2,%3};"
                : "+f"(c[nt][0]), "+f"(c[nt][1]), "+f"(c[nt][2]), "+f"(c[nt][3])
                : "r"(a0), "r"(a1), "r"(a2), "r"(a3), "r"(b0), "r"(b1));
        }
    }
    __syncthreads();

    float* sout = reinterpret_cast<float*>(smem);
    {
        const int r0 = wid * 16 + (lane >> 2);
        const int r1 = r0 + 8;
#pragma unroll
        for (int nt = 0; nt < 16; nt++) {
            const int col = nt * 8 + (lane & 3) * 2;
            const float bb0 = sbias[col], bb1 = sbias[col + 1];
            sout[r0 * 132 + col]     = c[nt][0] + bb0;
            sout[r0 * 132 + col + 1] = c[nt][1] + bb1;
            sout[r1 * 132 + col]     = c[nt][2] + bb0;
            sout[r1 * 132 + col + 1] = c[nt][3] + bb1;
        }
    }
    __syncthreads();

    for (int i = tx; i < 128 * 32; i += 256) {
        const int t = i >> 5, q = i & 31;
        float4 v = *(const float4*)&sout[t * 132 + q * 4];
        const int dir = q >> 4, j4 = (q & 15) * 4;
        float* plane = dir ? g_xw1 : g_xw0;
        *(float4*)&plane[(size_t)(b * TT + t0 + t) * HH + j4] = v;
    }
}

// ============================================================================
// Scan pass1: float4-vectorized; now also writes per-chunk end value g_hl.
// ============================================================================
__global__ __launch_bounds__(128) void scan_pass1(
    const float* __restrict__ Whhf, const float* __restrict__ Whhb)
{
    const int blk = blockIdx.x;          // 256 = b*2 + dir
    const int b = blk >> 1, dir = blk & 1;
    const int tx = threadIdx.x;
    const int jg = tx & 15, chunk = tx >> 4;
    const int j0 = jg * 4;
    const float* W = dir ? Whhb : Whhf;

    __shared__ int sOK;
    if (tx == 0) sOK = 1;
    __syncthreads();
    if (!row_is_identity(W, tx & 63)) atomicAnd(&sOK, 0);
    __syncthreads();

    const float* xw = dir ? g_xw1 : g_xw0;
    float*       hp = dir ? g_h1  : g_h0;

    if (sOK) {
        const int tstart = dir ? (TT - 1 - chunk * CLEN) : chunk * CLEN;
        const ptrdiff_t step = dir ? -(ptrdiff_t)HH : (ptrdiff_t)HH;
        const float* xp = xw + (size_t)(b * TT + tstart) * HH + j0;
        float*       hw = hp + (size_t)(b * TT + tstart) * HH + j0;
        float4 S = make_float4(0.f, 0.f, 0.f, 0.f);
        float4 h = make_float4(0.f, 0.f, 0.f, 0.f);
        for (int g = 0; g < CLEN / 8; g++) {
            float4 v[8];
#pragma unroll
            for (int u = 0; u < 8; u++) v[u] = *(const float4*)&xp[step * u];
#pragma unroll
            for (int u = 0; u < 8; u++) {
                S.x += v[u].x; S.y += v[u].y; S.z += v[u].z; S.w += v[u].w;
                h.x = fmaxf(v[u].x + h.x, 0.0f);
                h.y = fmaxf(v[u].y + h.y, 0.0f);
                h.z = fmaxf(v[u].z + h.z, 0.0f);
                h.w = fmaxf(v[u].w + h.w, 0.0f);
                *(float4*)&hw[step * u] = h;
            }
            xp += step * 8; hw += step * 8;
        }
        const int chain0 = b * 128 + dir * 64 + j0;
        g_S [((chain0 + 0) << 3) + chunk] = S.x;
        g_S [((chain0 + 1) << 3) + chunk] = S.y;
        g_S [((chain0 + 2) << 3) + chunk] = S.z;
        g_S [((chain0 + 3) << 3) + chunk] = S.w;
        g_hl[((chain0 + 0) << 3) + chunk] = h.x;
        g_hl[((chain0 + 1) << 3) + chunk] = h.y;
        g_hl[((chain0 + 2) << 3) + chunk] = h.z;
        g_hl[((chain0 + 3) << 3) + chunk] = h.w;
    } else {
        __shared__ float shv[HH];
        float wrow[HH];
        if (tx < HH) {
#pragma unroll
            for (int k = 0; k < HH; k++) wrow[k] = W[tx * HH + k];
            shv[tx] = 0.0f;
        }
        __syncthreads();
        for (int t = 0; t < TT; t++) {
            const int tt = dir ? (TT - 1 - t) : t;
            float acc = 0.0f;
            if (tx < HH) {
                acc = xw[(size_t)(b * TT + tt) * HH + tx];
#pragma unroll
                for (int k = 0; k < HH; k++) acc += wrow[k] * shv[k];
                acc = fmaxf(acc, 0.0f);
            }
            __syncthreads();
            if (tx < HH) {
                shv[tx] = acc;
                hp[(size_t)(b * TT + tt) * HH + tx] = acc;
            }
            __syncthreads();
        }
    }
}

// ============================================================================
// pass2: 8-step boundary scan per chain, reading small contiguous g_S/g_hl.
// ============================================================================
__global__ __launch_bounds__(256) void scan_pass2(
    const float* __restrict__ Whhf, const float* __restrict__ Whhb)
{
    const int tx = threadIdx.x;
    const int chain = blockIdx.x * 256 + tx;

    __shared__ int sOKd[2];
    if (tx < 2) sOKd[tx] = 1;
    __syncthreads();
    {
        const int cd = (tx >> 6) & 1;
        const float* Wc = cd ? Whhb : Whhf;
        if (!row_is_identity(Wc, tx & 63)) atomicAnd(&sOKd[cd], 0);
    }
    __syncthreads();
    if (!sOKd[(chain >> 6) & 1]) return;

    float hin = 0.0f;
#pragma unroll
    for (int c = 0; c < CHK; c++) {
        g_hin[chain * CHK + c] = hin;
        hin = fmaxf(g_S[chain * CHK + c] + hin, g_hl[chain * CHK + c]);
    }
}

// ============================================================================
// Scan pass3: float4-vectorized fix-up (R13 measured-best, unchanged).
// ============================================================================
__global__ __launch_bounds__(128) void scan_pass3(
    const float* __restrict__ Whhf, const float* __restrict__ Whhb)
{
    const int blk = blockIdx.x;          // 256 = b*2 + dir
    const int b = blk >> 1, dir = blk & 1;
    const int tx = threadIdx.x;
    const int jg = tx & 15, chunk = tx >> 4;
    const int j0 = jg * 4;
    const float* W = dir ? Whhb : Whhf;

    __shared__ int sOK;
    if (tx == 0) sOK = 1;
    __syncthreads();
    if (!row_is_identity(W, tx & 63)) atomicAnd(&sOK, 0);
    __syncthreads();
    if (!sOK) return;
    if (chunk == 0) return;

    const int chain0 = b * 128 + dir * 64 + j0;
    float4 hin;
    hin.x = g_hin[((chain0 + 0) << 3) + chunk];
    hin.y = g_hin[((chain0 + 1) << 3) + chunk];
    hin.z = g_hin[((chain0 + 2) << 3) + chunk];
    hin.w = g_hin[((chain0 + 3) << 3) + chunk];
    if (hin.x == 0.0f && hin.y == 0.0f && hin.z == 0.0f && hin.w == 0.0f) return;

    const float* xw = dir ? g_xw1 : g_xw0;
    float*       hp = dir ? g_h1  : g_h0;
    const int tstart = dir ? (TT - 1 - chunk * CLEN) : chunk * CLEN;
    const ptrdiff_t step = dir ? -(ptrdiff_t)HH : (ptrdiff_t)HH;
    const float* xp = xw + (size_t)(b * TT + tstart) * HH + j0;
    float*       hw = hp + (size_t)(b * TT + tstart) * HH + j0;
    float4 S = make_float4(0.f, 0.f, 0.f, 0.f);
    for (int g = 0; g < CLEN / 8; g++) {
        float4 v[8], hl[8];
#pragma unroll
        for (int u = 0; u < 8; u++) v[u]  = *(const float4*)&xp[step * u];
#pragma unroll
        for (int u = 0; u < 8; u++) hl[u] = *(const float4*)&hw[step * u];
#pragma unroll
        for (int u = 0; u < 8; u++) {
            S.x += v[u].x; S.y += v[u].y; S.z += v[u].z; S.w += v[u].w;
            float4 o;
            o.x = fmaxf(S.x + hin.x, hl[u].x);
            o.y = fmaxf(S.y + hin.y, hl[u].y);
            o.z = fmaxf(S.z + hin.z, hl[u].z);
            o.w = fmaxf(S.w + hin.w, hl[u].w);
            *(float4*)&hw[step * u] = o;
        }
        xp += step * 8; hw += step * 8;
    }
}

// ============================================================================
// MLP head: 64-row tiles at occupancy 2 (SMEM 101.4 KB/CTA).
// 8 warps = 4 m-tiles (16 rows each) x 2 n-halves (64 n each).
// A' [64 x (Hhi|Hlo)] pitch 528; B' [128 x (Whi|Wlo)] pitch 528.
// Paired-B ldmatrix.x4 (2 n-tiles/instr), k-block remap as before.
// Cross-half reduction via tiny static SMEM.
// ============================================================================
constexpr int APITCH = 528;
constexpr int SM_A   = 0;
constexpr int SM_B   = 64 * APITCH;            // 33792
constexpr int SM_TOT = SM_B + 128 * APITCH;    // 101376

__global__ __launch_bounds__(256, 2)
void mlp_mma_kernel(const float* __restrict__ ff0b,
                    const float* __restrict__ ff1w,
                    const float* __restrict__ ff1b,
                    float* __restrict__ out)
{
    extern __shared__ __align__(128) char smem[];
    __shared__ float sb0[128], sw1[128];
    __shared__ float sPart[8][16];

    const int tx   = threadIdx.x;
    const int wid  = tx >> 5;
    const int lane = tx & 31;
    const int row0 = blockIdx.x * 64;
    const int mt   = wid & 3;            // m-tile (16 rows)
    const int nh   = wid >> 2;           // n-half (64 cols)

    if (tx < 128) { sb0[tx] = ff0b[tx]; sw1[tx] = ff1w[tx]; }

    // copy B' image: 4224 float4
    {
        const float4* src = reinterpret_cast<const float4*>(g_Bimg);
        float4* dst = reinterpret_cast<float4*>(smem + SM_B);
        for (int i = tx; i < (128 * APITCH) / 16; i += 256) dst[i] = src[i];
    }

    // build deduped A' = [Hhi | Hlo], 64 rows: thread -> (row tx>>2, quarter)
    // quarter 0: Hhi cols 0-63 (g_h0), 1: Hhi cols 64-127 (g_h1),
    //         2: Hlo cols 0-63,        3: Hlo cols 64-127
    {
        const int r = tx >> 2, quarter = tx & 3;
        const int dirq = quarter & 1;
        const int loq  = quarter >> 1;
        const float* hp = (dirq ? g_h1 : g_h0) + (size_t)(row0 + r) * HH;
        float hv[64];
#pragma unroll
        for (int q = 0; q < 16; q++) *(float4*)&hv[q * 4] = *(const float4*)&hp[q * 4];
        char* A = smem + SM_A + r * APITCH + loq * 256 + dirq * 128;
        if (loq == 0) {
#pragma unroll
            for (int kq = 0; kq < 16; kq++) {
                const int c = kq * 4;
                __nv_bfloat162 q0 = make_bfloat162(__float2bfloat16(hv[c]),
                                                   __float2bfloat16(hv[c + 1]));
                __nv_bfloat162 q1 = make_bfloat162(__float2bfloat16(hv[c + 2]),
                                                   __float2bfloat16(hv[c + 3]));
                u64 pq = ((u64)(*reinterpret_cast<uint32_t*>(&q1)) << 32)
                       |  (u64)(*reinterpret_cast<uint32_t*>(&q0));
                *(u64*)(A + c * 2) = pq;
            }
        } else {
#pragma unroll
            for (int kq = 0; kq < 16; kq++) {
                const int c = kq * 4;
                __nv_bfloat16 b0 = __float2bfloat16(hv[c]);
                __nv_bfloat16 b1 = __float2bfloat16(hv[c + 1]);
                __nv_bfloat16 b2 = __float2bfloat16(hv[c + 2]);
                __nv_bfloat16 b3 = __float2bfloat16(hv[c + 3]);
                __nv_bfloat162 l01 = make_bfloat162(
                    __float2bfloat16(hv[c]     - __bfloat162float(b0)),
                    __float2bfloat16(hv[c + 1] - __bfloat162float(b1)));
                __nv_bfloat162 l23 = make_bfloat162(
                    __float2bfloat16(hv[c + 2] - __bfloat162float(b2)),
                    __float2bfloat16(hv[c + 3] - __bfloat162float(b3)));
                u64 lq = ((u64)(*reinterpret_cast<uint32_t*>(&l23)) << 32)
                       |  (u64)(*reinterpret_cast<uint32_t*>(&l01));
                *(u64*)(A + c * 2) = lq;
            }
        }
    }
    __syncthreads();

    // mainloop: warp = (m-tile mt) x (n-half nh); paired-B ldmatrix.x4
    const uint32_t aAddr = smem_u32(smem) + SM_A
        + (uint32_t)(mt * 16 + (lane & 15)) * APITCH + (uint32_t)(lane >> 4) * 16;
    const uint32_t bAddr = smem_u32(smem) + SM_B
        + (uint32_t)(nh * 64 + (lane & 7) + ((lane >> 4) << 3)) * APITCH
        + (uint32_t)((lane >> 3) & 1) * 16;

    float c[8][4];
#pragma unroll
    for (int nt = 0; nt < 8; nt++)
#pragma unroll
        for (int q = 0; q < 4; q++) c[nt][q] = 0.0f;

#pragma unroll 1
    for (int kk = 0; kk < 24; kk++) {
        const uint32_t ao = (uint32_t)((kk < 8)  ? kk : (kk - 8))  * 32;
        const uint32_t bo = (uint32_t)((kk < 16) ? kk : (kk - 16)) * 32;
        uint32_t a0, a1, a2, a3;
        asm volatile("ldmatrix.sync.aligned.m8n8.x4.shared.b16 {%0,%1,%2,%3}, [%4];"
                     : "=r"(a0), "=r"(a1), "=r"(a2), "=r"(a3)
                     : "r"(aAddr + ao));
#pragma unroll
        for (int np = 0; np < 4; np++) {
            uint32_t b0, b1, b2, b3;
            asm volatile("ldmatrix.sync.aligned.m8n8.x4.shared.b16 {%0,%1,%2,%3}, [%4];"
                         : "=r"(b0), "=r"(b1), "=r"(b2), "=r"(b3)
                         : "r"(bAddr + (uint32_t)np * 16 * APITCH + bo));
            const int nt0 = np * 2, nt1 = nt0 + 1;
            asm volatile(
                "mma.sync.aligned.m16n8k16.row.col.f32.bf16.bf16.f32 "
                "{%0,%1,%2,%3}, {%4,%5,%6,%7}, {%8,%9}, {%0,%1,%2,%3};"
                : "+f"(c[nt0][0]), "+f"(c[nt0][1]), "+f"(c[nt0][2]), "+f"(c[nt0][3])
                : "r"(a0), "r"(a1), "r"(a2), "r"(a3), "r"(b0), "r"(b1));
            asm volatile(
                "mma.sync.aligned.m16n8k16.row.col.f32.bf16.bf16.f32 "
                "{%0,%1,%2,%3}, {%4,%5,%6,%7}, {%8,%9}, {%0,%1,%2,%3};"
                : "+f"(c[nt1][0]), "+f"(c[nt1][1]), "+f"(c[nt1][2]), "+f"(c[nt1][3])
                : "r"(a0), "r"(a1), "r"(a2), "r"(a3), "r"(b2), "r"(b3));
        }
    }

    // epilogue: per-warp partial over its 8 n-tiles (within its n-half)
    float y0 = 0.0f, y1 = 0.0f;
#pragma unroll
    for (int nt = 0; nt < 8; nt++) {
        const int col = nh * 64 + nt * 8 + (lane & 3) * 2;
        const float bb0 = sb0[col], bb1 = sb0[col + 1];
        const float ww0 = sw1[col], ww1 = sw1[col + 1];
        float z;
        z = c[nt][0] + bb0; y0 = fmaf(ww0, z > 0.0f ? z : 0.01f * z, y0);
        z = c[nt][1] + bb1; y0 = fmaf(ww1, z > 0.0f ? z : 0.01f * z, y0);
        z = c[nt][2] + bb0; y1 = fmaf(ww0, z > 0.0f ? z : 0.01f * z, y1);
        z = c[nt][3] + bb1; y1 = fmaf(ww1, z > 0.0f ? z : 0.01f * z, y1);
    }
    y0 += __shfl_xor_sync(0xffffffffu, y0, 1);
    y1 += __shfl_xor_sync(0xffffffffu, y1, 1);
    y0 += __shfl_xor_sync(0xffffffffu, y0, 2);
    y1 += __shfl_xor_sync(0xffffffffu, y1, 2);
    if ((lane & 3) == 0) {
        const int rr = lane >> 2;           // 0..7
        sPart[wid][rr]     = y0;
        sPart[wid][rr + 8] = y1;
    }
    __syncthreads();
    if (tx < 64) {
        const int mt2 = tx >> 4, rr = tx & 15;
        out[row0 + mt2 * 16 + rr] = sPart[mt2][rr] + sPart[mt2 + 4][rr] + ff1b[0];
    }
}

// ============================================================================
extern "C" void kernel_launch(void* const* d_in, const int* in_sizes, int n_in,
                              void* d_out, int out_size)
{
    const float* x    = (const float*)d_in[0];
    const float* Wihf = (const float*)d_in[1];
    const float* Whhf = (const float*)d_in[2];
    const float* bihf = (const float*)d_in[3];
    const float* bhhf = (const float*)d_in[4];
    const float* Wihb = (const float*)d_in[5];
    const float* Whhb = (const float*)d_in[6];
    const float* bihb = (const float*)d_in[7];
    const float* bhhb = (const float*)d_in[8];
    const float* ff0w = (const float*)d_in[9];
    const float* ff0b = (const float*)d_in[10];
    const float* ff1w = (const float*)d_in[11];
    const float* ff1b = (const float*)d_in[12];

    cudaFuncSetAttribute(mlp_mma_kernel,
                         cudaFuncAttributeMaxDynamicSharedMemorySize, SM_TOT);
    cudaFuncSetAttribute(proj_mma_kernel,
                         cudaFuncAttributeMaxDynamicSharedMemorySize, PSM_TOT);

    prep_kernel<<<1, 512>>>(ff0w, Wihf, Wihb, bihf, bhhf, bihb, bhhb);
    proj_mma_kernel<<<2048, 256, PSM_TOT>>>(x);
    scan_pass1<<<256, 128>>>(Whhf, Whhb);
    scan_pass2<<<64, 256>>>(Whhf, Whhb);
    scan_pass3<<<256, 128>>>(Whhf, Whhb);
    mlp_mma_kernel<<<4096, 256, SM_TOT>>>(ff0b, ff1w, ff1b, (float*)d_out);
}

// round 15
// speedup vs baseline: 1.1213x; 1.1213x over previous
#include <cuda_runtime.h>
#include <cuda_bf16.h>
#include <cstdint>
#include <cstddef>

// Problem constants (fixed by the reference)
#define BB 128
#define TT 2048
#define II 32
#define HH 64
constexpr int NROWS  = BB * TT;        // 262144
constexpr int NELEM  = NROWS * HH;     // 16,777,216 per plane
constexpr int CHK    = 8;              // chunks per chain (scan split)
constexpr int CLEN   = TT / CHK;       // 256

// Scratch (device globals — no runtime allocation allowed).
__device__ float g_xw0[NELEM];
__device__ float g_xw1[NELEM];
__device__ float g_h0[NELEM];
__device__ float g_h1[NELEM];

// Deduped B' image for the MMA MLP: 128 rows x [Whi(128)|Wlo(128)] bf16,
// pitch 264 elems (528 B)
constexpr int BPITCHE = 264;
__device__ uint32_t g_Bimg[128 * BPITCHE / 2];   // 67584 bytes

// B' image for the MMA projection: 128 rows x 104 bf16 (pitch 208 B),
// K = [Whi(32) | Wlo(32) | Whi(32)]
constexpr int PPITCHE = 104;
__device__ uint32_t g_BimgP[128 * PPITCHE / 2];
__device__ float    g_biasP[128];

typedef unsigned long long u64;

__device__ __forceinline__ bool row_is_identity(const float* W, int j) {
    bool ok = true;
#pragma unroll
    for (int k = 0; k < HH; k++) ok &= (W[j * HH + k] == ((k == j) ? 1.0f : 0.0f));
    return ok;
}

__device__ __forceinline__ uint32_t smem_u32(const void* p) {
    uint32_t a;
    asm("{ .reg .u64 t; cvta.to.shared.u64 t, %1; cvt.u32.u64 %0, t; }"
        : "=r"(a) : "l"(p));
    return a;
}

// ============================================================================
// Prep: build both B' images + proj bias vector.
// ============================================================================
__global__ __launch_bounds__(512) void prep_kernel(
    const float* __restrict__ ff0w,
    const float* __restrict__ Wihf, const float* __restrict__ Wihb,
    const float* __restrict__ bihf, const float* __restrict__ bhhf,
    const float* __restrict__ bihb, const float* __restrict__ bhhb)
{
    const int tx = threadIdx.x;
    const int j  = tx >> 2;
    const int kq = tx & 3;

    // MLP image (deduped): [128 j][256 k], pitch 264; K = [Whi | Wlo]
    for (int kp = kq * 32; kp < (kq + 1) * 32; kp++) {
        const int c = 2 * kp;
        const int lo_type = (c >= 128);
        const int sk = lo_type ? (c - 128) : c;
        float w0 = ff0w[j * 128 + sk], w1 = ff0w[j * 128 + sk + 1];
        __nv_bfloat16 h0 = __float2bfloat16(w0), h1 = __float2bfloat16(w1);
        __nv_bfloat16 o0, o1;
        if (lo_type) {
            o0 = __float2bfloat16(w0 - __bfloat162float(h0));
            o1 = __float2bfloat16(w1 - __bfloat162float(h1));
        } else { o0 = h0; o1 = h1; }
        __nv_bfloat162 p2 = make_bfloat162(o0, o1);
        g_Bimg[j * (BPITCHE / 2) + kp] = *reinterpret_cast<uint32_t*>(&p2);
    }

    // proj image: [128 n][96 k], pitch 104; K = [Whi|Wlo|Whi]; n = dir*64+jr
    {
        const int n = j;
        const int dir = n >> 6, jr = n & 63;
        const float* W = dir ? Wihb : Wihf;
        for (int kp = kq * 12; kp < (kq + 1) * 12; kp++) {
            const int c = 2 * kp;
            int sk, lo_type;
            if (c < 32)      { sk = c;      lo_type = 0; }
            else if (c < 64) { sk = c - 32; lo_type = 1; }
            else             { sk = c - 64; lo_type = 0; }
            float w0 = W[jr * II + sk], w1 = W[jr * II + sk + 1];
            __nv_bfloat16 h0 = __float2bfloat16(w0), h1 = __float2bfloat16(w1);
            __nv_bfloat16 o0, o1;
            if (lo_type) {
                o0 = __float2bfloat16(w0 - __bfloat162float(h0));
                o1 = __float2bfloat16(w1 - __bfloat162float(h1));
            } else { o0 = h0; o1 = h1; }
            __nv_bfloat162 p2 = make_bfloat162(o0, o1);
            g_BimgP[n * (PPITCHE / 2) + kp] = *reinterpret_cast<uint32_t*>(&p2);
        }
        if (kq == 0)
            g_biasP[n] = dir ? (bihb[jr] + bhhb[jr]) : (bihf[jr] + bhhf[jr]);
    }
}

// ============================================================================
// Kernel 1: input projection via mma.sync (R13 measured-best, unchanged).
// ============================================================================
constexpr int PAPITCH = 208;
constexpr int PSM_A   = 0;
constexpr int PSM_B   = 128 * PAPITCH;              // 26624
constexpr int PSM_AB  = PSM_B + 128 * PAPITCH;      // 53248
constexpr int PSM_OUT = 128 * 132 * 4;              // 67584
constexpr int PSM_TOT = PSM_OUT > PSM_AB ? PSM_OUT : PSM_AB;

__global__ __launch_bounds__(256, 2)
void proj_mma_kernel(const float* __restrict__ x)
{
    extern __shared__ __align__(128) char smem[];
    __shared__ float sbias[128];

    const int tx   = threadIdx.x;
    const int wid  = tx >> 5;
    const int lane = tx & 31;
    const int row0 = blockIdx.x * 128;
    const int b    = row0 >> 11;            // TT = 2048
    const int t0   = row0 & (TT - 1);

    if (tx < 128) sbias[tx] = g_biasP[tx];

    {
        const float4* src = reinterpret_cast<const float4*>(g_BimgP);
        float4* dst = reinterpret_cast<float4*>(smem + PSM_B);
        for (int i = tx; i < PSM_B / 16; i += 256) dst[i] = src[i];
    }

    {
        const int r = tx >> 1, half = tx & 1;
        const float* px = &x[(size_t)(b * TT + t0 + r) * II];
        float hv[II];
#pragma unroll
        for (int q = 0; q < 8; q++) *(float4*)&hv[q * 4] = *(const float4*)&px[q * 4];
        char* A = smem + PSM_A + r * PAPITCH;
        if (half == 0) {
#pragma unroll
            for (int kq = 0; kq < 8; kq++) {
                const int c = kq * 4;
                __nv_bfloat162 q0 = make_bfloat162(__float2bfloat16(hv[c]),
                                                   __float2bfloat16(hv[c + 1]));
                __nv_bfloat162 q1 = make_bfloat162(__float2bfloat16(hv[c + 2]),
                                                   __float2bfloat16(hv[c + 3]));
                u64 pq = ((u64)(*reinterpret_cast<uint32_t*>(&q1)) << 32)
                       |  (u64)(*reinterpret_cast<uint32_t*>(&q0));
                *(u64*)(A + c * 2) = pq;
            }
        } else {
#pragma unroll
            for (int kq = 0; kq < 8; kq++) {
                const int c = kq * 4;
                __nv_bfloat16 b0 = __float2bfloat16(hv[c]);
                __nv_bfloat16 b1 = __float2bfloat16(hv[c + 1]);
                __nv_bfloat16 b2 = __float2bfloat16(hv[c + 2]);
                __nv_bfloat16 b3 = __float2bfloat16(hv[c + 3]);
                __nv_bfloat162 h01 = make_bfloat162(b0, b1);
                __nv_bfloat162 h23 = make_bfloat162(b2, b3);
                u64 hq = ((u64)(*reinterpret_cast<uint32_t*>(&h23)) << 32)
                       |  (u64)(*reinterpret_cast<uint32_t*>(&h01));
                __nv_bfloat162 l01 = make_bfloat162(
                    __float2bfloat16(hv[c]     - __bfloat162float(b0)),
                    __float2bfloat16(hv[c + 1] - __bfloat162float(b1)));
                __nv_bfloat162 l23 = make_bfloat162(
                    __float2bfloat16(hv[c + 2] - __bfloat162float(b2)),
                    __float2bfloat16(hv[c + 3] - __bfloat162float(b3)));
                u64 lq = ((u64)(*reinterpret_cast<uint32_t*>(&l23)) << 32)
                       |  (u64)(*reinterpret_cast<uint32_t*>(&l01));
                *(u64*)(A + (c + 32) * 2) = hq;
                *(u64*)(A + (c + 64) * 2) = lq;
            }
        }
    }
    __syncthreads();

    const uint32_t aAddr = smem_u32(smem) + PSM_A
        + (uint32_t)(wid * 16 + (lane & 15)) * PAPITCH + (uint32_t)(lane >> 4) * 16;
    const uint32_t bAddr = smem_u32(smem) + PSM_B
        + (uint32_t)(lane & 7) * PAPITCH + (uint32_t)((lane >> 3) & 1) * 16;

    float c[16][4];
#pragma unroll
    for (int nt = 0; nt < 16; nt++)
#pragma unroll
        for (int q = 0; q < 4; q++) c[nt][q] = 0.0f;

#pragma unroll
    for (int kk = 0; kk < 6; kk++) {
        uint32_t a0, a1, a2, a3;
        asm volatile("ldmatrix.sync.aligned.m8n8.x4.shared.b16 {%0,%1,%2,%3}, [%4];"
                     : "=r"(a0), "=r"(a1), "=r"(a2), "=r"(a3)
                     : "r"(aAddr + kk * 32));
#pragma unroll
        for (int nt = 0; nt < 16; nt++) {
            uint32_t b0, b1;
            asm volatile("ldmatrix.sync.aligned.m8n8.x2.shared.b16 {%0,%1}, [%2];"
                         : "=r"(b0), "=r"(b1)
                         : "r"(bAddr + (uint32_t)nt * 8 * PAPITCH + kk * 32));
            asm volatile(
                "mma.sync.aligned.m16n8k16.row.col.f32.bf16.bf16.f32 "
                "{%0,%1,%2,%3}, {%4,%5,%6,%7}, {%8,%9}, {%0,%1,%2,%3};"
                : "+f"(c[nt][0]), "+f"(c[nt][1]), "+f"(c[nt][2]), "+f"(c[nt][3])
                : "r"(a0), "r"(a1), "r"(a2), "r"(a3), "r"(b0), "r"(b1));
        }
    }
    __syncthreads();

    float* sout = reinterpret_cast<float*>(smem);
    {
        const int r0 = wid * 16 + (lane >> 2);
        const int r1 = r0 + 8;
#pragma unroll
        for (int nt = 0; nt < 16; nt++) {
            const int col = nt * 8 + (lane & 3) * 2;
            const float bb0 = sbias[col], bb1 = sbias[col + 1];
            sout[r0 * 132 + col]     = c[nt][0] + bb0;
            sout[r0 * 132 + col + 1] = c[nt][1] + bb1;
            sout[r1 * 132 + col]     = c[nt][2] + bb0;
            sout[r1 * 132 + col + 1] = c[nt][3] + bb1;
        }
    }
    __syncthreads();

    for (int i = tx; i < 128 * 32; i += 256) {
        const int t = i >> 5, q = i & 31;
        float4 v = *(const float4*)&sout[t * 132 + q * 4];
        const int dir = q >> 4, j4 = (q & 15) * 4;
        float* plane = dir ? g_xw1 : g_xw0;
        *(float4*)&plane[(size_t)(b * TT + t0 + t) * HH + j4] = v;
    }
}

// ============================================================================
// Fused scan: one block per (b, dir) holds ALL chunks of its 64 chains, so
// the three passes fuse with SMEM glue:
//   phase 1: per-chunk local scan (float4, 4 chains/thread) -> h plane;
//            chunk sum S and end value h_end staged in SMEM.
//   phase 2: 64 threads run the 8-step max-plus boundary scan in SMEM.
//   phase 3: per-chunk fix-up h = max(PS + hin, h_local), hin from SMEM;
//            exact hin==0 skip (fp monotonicity: h_local >= PS).
// General-W fallback unchanged (full serial matvec per block).
// ============================================================================
__global__ __launch_bounds__(128) void scan_fused(
    const float* __restrict__ Whhf, const float* __restrict__ Whhb)
{
    __shared__ float sS  [CHK][64];
    __shared__ float sHl [CHK][64];
    __shared__ float sHin[CHK][64];
    __shared__ int sOK;

    const int blk = blockIdx.x;          // 256 = b*2 + dir
    const int b = blk >> 1, dir = blk & 1;
    const int tx = threadIdx.x;
    const int jg = tx & 15, chunk = tx >> 4;
    const int j0 = jg * 4;
    const float* W = dir ? Whhb : Whhf;

    if (tx == 0) sOK = 1;
    __syncthreads();
    if (!row_is_identity(W, tx & 63)) atomicAnd(&sOK, 0);
    __syncthreads();

    const float* xw = dir ? g_xw1 : g_xw0;
    float*       hp = dir ? g_h1  : g_h0;

    if (sOK) {
        const int tstart = dir ? (TT - 1 - chunk * CLEN) : chunk * CLEN;
        const ptrdiff_t step = dir ? -(ptrdiff_t)HH : (ptrdiff_t)HH;

        // phase 1: local scan
        {
            const float* xp = xw + (size_t)(b * TT + tstart) * HH + j0;
            float*       hw = hp + (size_t)(b * TT + tstart) * HH + j0;
            float4 S = make_float4(0.f, 0.f, 0.f, 0.f);
            float4 h = make_float4(0.f, 0.f, 0.f, 0.f);
            for (int g = 0; g < CLEN / 8; g++) {
                float4 v[8];
#pragma unroll
                for (int u = 0; u < 8; u++) v[u] = *(const float4*)&xp[step * u];
#pragma unroll
                for (int u = 0; u < 8; u++) {
                    S.x += v[u].x; S.y += v[u].y; S.z += v[u].z; S.w += v[u].w;
                    h.x = fmaxf(v[u].x + h.x, 0.0f);
                    h.y = fmaxf(v[u].y + h.y, 0.0f);
                    h.z = fmaxf(v[u].z + h.z, 0.0f);
                    h.w = fmaxf(v[u].w + h.w, 0.0f);
                    *(float4*)&hw[step * u] = h;
                }
                xp += step * 8; hw += step * 8;
            }
            *(float4*)&sS [chunk][j0] = S;
            *(float4*)&sHl[chunk][j0] = h;
        }
        __syncthreads();

        // phase 2: boundary scan (thread = chain j)
        if (tx < 64) {
            float hin = 0.0f;
#pragma unroll
            for (int c = 0; c < CHK; c++) {
                sHin[c][tx] = hin;
                hin = fmaxf(sS[c][tx] + hin, sHl[c][tx]);
            }
        }
        __syncthreads();

        // phase 3: fix-up (chunk 0 is exact already)
        if (chunk > 0) {
            float4 hin = *(const float4*)&sHin[chunk][j0];
            if (!(hin.x == 0.0f && hin.y == 0.0f && hin.z == 0.0f && hin.w == 0.0f)) {
                const float* xp = xw + (size_t)(b * TT + tstart) * HH + j0;
                float*       hw = hp + (size_t)(b * TT + tstart) * HH + j0;
                float4 S = make_float4(0.f, 0.f, 0.f, 0.f);
                for (int g = 0; g < CLEN / 8; g++) {
                    float4 v[8], hl[8];
#pragma unroll
                    for (int u = 0; u < 8; u++) v[u]  = *(const float4*)&xp[step * u];
#pragma unroll
                    for (int u = 0; u < 8; u++) hl[u] = *(const float4*)&hw[step * u];
#pragma unroll
                    for (int u = 0; u < 8; u++) {
                        S.x += v[u].x; S.y += v[u].y; S.z += v[u].z; S.w += v[u].w;
                        float4 o;
                        o.x = fmaxf(S.x + hin.x, hl[u].x);
                        o.y = fmaxf(S.y + hin.y, hl[u].y);
                        o.z = fmaxf(S.z + hin.z, hl[u].z);
                        o.w = fmaxf(S.w + hin.w, hl[u].w);
                        *(float4*)&hw[step * u] = o;
                    }
                    xp += step * 8; hw += step * 8;
                }
            }
        }
    } else {
        // general fallback: full serial matvec scan for this (b, dir)
        __shared__ float shv[HH];
        float wrow[HH];
        if (tx < HH) {
#pragma unroll
            for (int k = 0; k < HH; k++) wrow[k] = W[tx * HH + k];
            shv[tx] = 0.0f;
        }
        __syncthreads();
        for (int t = 0; t < TT; t++) {
            const int tt = dir ? (TT - 1 - t) : t;
            float acc = 0.0f;
            if (tx < HH) {
                acc = xw[(size_t)(b * TT + tt) * HH + tx];
#pragma unroll
                for (int k = 0; k < HH; k++) acc += wrow[k] * shv[k];
                acc = fmaxf(acc, 0.0f);
            }
            __syncthreads();
            if (tx < HH) {
                shv[tx] = acc;
                hp[(size_t)(b * TT + tt) * HH + tx] = acc;
            }
            __syncthreads();
        }
    }
}

// ============================================================================
// MLP head via warp-level mma.sync (R13 measured-best version, unchanged):
// 128-row tiles, deduped split-K images, paired-B ldmatrix.x4.
// ============================================================================
constexpr int APITCH = 528;
constexpr int SM_A   = 0;
constexpr int SM_B   = 128 * APITCH;           // 67584
constexpr int SM_TOT = SM_B + 128 * APITCH;    // 135168

__global__ __launch_bounds__(256, 1)
void mlp_mma_kernel(const float* __restrict__ ff0b,
                    const float* __restrict__ ff1w,
                    const float* __restrict__ ff1b,
                    float* __restrict__ out)
{
    extern __shared__ __align__(128) char smem[];
    __shared__ float sb0[128], sw1[128];

    const int tx   = threadIdx.x;
    const int wid  = tx >> 5;
    const int lane = tx & 31;
    const int row0 = blockIdx.x * 128;

    if (tx < 128) { sb0[tx] = ff0b[tx]; sw1[tx] = ff1w[tx]; }

    // copy B' image: 4224 float4
    {
        const float4* src = reinterpret_cast<const float4*>(g_Bimg);
        float4* dst = reinterpret_cast<float4*>(smem + SM_B);
        for (int i = tx; i < SM_B / 16; i += 256) dst[i] = src[i];
    }

    // build deduped A' = [Hhi | Hlo] from h planes
    {
        const int r = tx >> 1, half = tx & 1;
        const float* p0 = &g_h0[(size_t)(row0 + r) * HH];
        const float* p1 = &g_h1[(size_t)(row0 + r) * HH];
        float hv[128];
#pragma unroll
        for (int q = 0; q < 16; q++) *(float4*)&hv[q * 4]      = *(const float4*)&p0[q * 4];
#pragma unroll
        for (int q = 0; q < 16; q++) *(float4*)&hv[64 + q * 4] = *(const float4*)&p1[q * 4];
        char* A = smem + SM_A + r * APITCH;
        if (half == 0) {
#pragma unroll
            for (int kq = 0; kq < 32; kq++) {
                const int c = kq * 4;
                __nv_bfloat162 q0 = make_bfloat162(__float2bfloat16(hv[c]),
                                                   __float2bfloat16(hv[c + 1]));
                __nv_bfloat162 q1 = make_bfloat162(__float2bfloat16(hv[c + 2]),
                                                   __float2bfloat16(hv[c + 3]));
                u64 pq = ((u64)(*reinterpret_cast<uint32_t*>(&q1)) << 32)
                       |  (u64)(*reinterpret_cast<uint32_t*>(&q0));
                *(u64*)(A + c * 2) = pq;
            }
        } else {
#pragma unroll
            for (int kq = 0; kq < 32; kq++) {
                const int c = kq * 4;
                __nv_bfloat16 b0 = __float2bfloat16(hv[c]);
                __nv_bfloat16 b1 = __float2bfloat16(hv[c + 1]);
                __nv_bfloat16 b2 = __float2bfloat16(hv[c + 2]);
                __nv_bfloat16 b3 = __float2bfloat16(hv[c + 3]);
                __nv_bfloat162 l01 = make_bfloat162(
                    __float2bfloat16(hv[c]     - __bfloat162float(b0)),
                    __float2bfloat16(hv[c + 1] - __bfloat162float(b1)));
                __nv_bfloat162 l23 = make_bfloat162(
                    __float2bfloat16(hv[c + 2] - __bfloat162float(b2)),
                    __float2bfloat16(hv[c + 3] - __bfloat162float(b3)));
                u64 lq = ((u64)(*reinterpret_cast<uint32_t*>(&l23)) << 32)
                       |  (u64)(*reinterpret_cast<uint32_t*>(&l01));
                *(u64*)(A + 256 + c * 2) = lq;
            }
        }
    }
    __syncthreads();

    // mainloop with k-block remap; B via paired ldmatrix.x4 (2 n-tiles)
    const uint32_t aAddr = smem_u32(smem) + SM_A
        + (uint32_t)(wid * 16 + (lane & 15)) * APITCH + (uint32_t)(lane >> 4) * 16;
    const uint32_t bAddr = smem_u32(smem) + SM_B
        + (uint32_t)((lane & 7) + ((lane >> 4) << 3)) * APITCH
        + (uint32_t)((lane >> 3) & 1) * 16;

    float c[16][4];
#pragma unroll
    for (int nt = 0; nt < 16; nt++)
#pragma unroll
        for (int q = 0; q < 4; q++) c[nt][q] = 0.0f;

#pragma unroll 1
    for (int kk = 0; kk < 24; kk++) {
        const uint32_t ao = (uint32_t)((kk < 8)  ? kk : (kk - 8))  * 32;
        const uint32_t bo = (uint32_t)((kk < 16) ? kk : (kk - 16)) * 32;
        uint32_t a0, a1, a2, a3;
        asm volatile("ldmatrix.sync.aligned.m8n8.x4.shared.b16 {%0,%1,%2,%3}, [%4];"
                     : "=r"(a0), "=r"(a1), "=r"(a2), "=r"(a3)
                     : "r"(aAddr + ao));
#pragma unroll
        for (int np = 0; np < 8; np++) {
            uint32_t b0, b1, b2, b3;
            asm volatile("ldmatrix.sync.aligned.m8n8.x4.shared.b16 {%0,%1,%2,%3}, [%4];"
                         : "=r"(b0), "=r"(b1), "=r"(b2), "=r"(b3)
                         : "r"(bAddr + (uint32_t)np * 16 * APITCH + bo));
            const int nt0 = np * 2, nt1 = nt0 + 1;
            asm volatile(
                "mma.sync.aligned.m16n8k16.row.col.f32.bf16.bf16.f32 "
                "{%0,%1,%2,%3}, {%4,%5,%6,%7}, {%8,%9}, {%0,%1,%2,%3};"
                : "+f"(c[nt0][0]), "+f"(c[nt0][1]), "+f"(c[nt0][2]), "+f"(c[nt0][3])
                : "r"(a0), "r"(a1), "r"(a2), "r"(a3), "r"(b0), "r"(b1));
            asm volatile(
                "mma.sync.aligned.m16n8k16.row.col.f32.bf16.bf16.f32 "
                "{%0,%1,%2,%3}, {%4,%5,%6,%7}, {%8,%9}, {%0,%1,%2,%3};"
                : "+f"(c[nt1][0]), "+f"(c[nt1][1]), "+f"(c[nt1][2]), "+f"(c[nt1][3])
                : "r"(a0), "r"(a1), "r"(a2), "r"(a3), "r"(b2), "r"(b3));
        }
    }

    // epilogue
    float y0 = 0.0f, y1 = 0.0f;
#pragma unroll
    for (int nt = 0; nt < 16; nt++) {
        const int col = nt * 8 + (lane & 3) * 2;
        const float bb0 = sb0[col], bb1 = sb0[col + 1];
        const float ww0 = sw1[col], ww1 = sw1[col + 1];
        float z;
        z = c[nt][0] + bb0; y0 = fmaf(ww0, z > 0.0f ? z : 0.01f * z, y0);
        z = c[nt][1] + bb1; y0 = fmaf(ww1, z > 0.0f ? z : 0.01f * z, y0);
        z = c[nt][2] + bb0; y1 = fmaf(ww0, z > 0.0f ? z : 0.01f * z, y1);
        z = c[nt][3] + bb1; y1 = fmaf(ww1, z > 0.0f ? z : 0.01f * z, y1);
    }
    y0 += __shfl_xor_sync(0xffffffffu, y0, 1);
    y1 += __shfl_xor_sync(0xffffffffu, y1, 1);
    y0 += __shfl_xor_sync(0xffffffffu, y0, 2);
    y1 += __shfl_xor_sync(0xffffffffu, y1, 2);
    if ((lane & 3) == 0) {
        const float fb = ff1b[0];
        const int r = row0 + wid * 16 + (lane >> 2);
        out[r]     = y0 + fb;
        out[r + 8] = y1 + fb;
    }
}

// ============================================================================
extern "C" void kernel_launch(void* const* d_in, const int* in_sizes, int n_in,
                              void* d_out, int out_size)
{
    const float* x    = (const float*)d_in[0];
    const float* Wihf = (const float*)d_in[1];
    const float* Whhf = (const float*)d_in[2];
    const float* bihf = (const float*)d_in[3];
    const float* bhhf = (const float*)d_in[4];
    const float* Wihb = (const float*)d_in[5];
    const float* Whhb = (const float*)d_in[6];
    const float* bihb = (const float*)d_in[7];
    const float* bhhb = (const float*)d_in[8];
    const float* ff0w = (const float*)d_in[9];
    const float* ff0b = (const float*)d_in[10];
    const float* ff1w = (const float*)d_in[11];
    const float* ff1b = (const float*)d_in[12];

    cudaFuncSetAttribute(mlp_mma_kernel,
                         cudaFuncAttributeMaxDynamicSharedMemorySize, SM_TOT);
    cudaFuncSetAttribute(proj_mma_kernel,
                         cudaFuncAttributeMaxDynamicSharedMemorySize, PSM_TOT);

    prep_kernel<<<1, 512>>>(ff0w, Wihf, Wihb, bihf, bhhf, bihb, bhhb);
    proj_mma_kernel<<<2048, 256, PSM_TOT>>>(x);
    scan_fused<<<256, 128>>>(Whhf, Whhb);
    mlp_mma_kernel<<<2048, 256, SM_TOT>>>(ff0b, ff1w, ff1b, (float*)d_out);
}

// round 16
// speedup vs baseline: 1.2860x; 1.1469x over previous
#include <cuda_runtime.h>
#include <cuda_bf16.h>
#include <cstdint>
#include <cstddef>

// Problem constants (fixed by the reference)
#define BB 128
#define TT 2048
#define II 32
#define HH 64
constexpr int NROWS  = BB * TT;        // 262144
constexpr int NELEM  = NROWS * HH;     // 16,777,216 per plane
constexpr int NCHAIN = BB * 2 * HH;    // 16384 scan chains
constexpr int CHK    = 8;              // chunks per chain
constexpr int CLEN   = 256;            // chunk length
constexpr int NHC    = 16;             // half-chunks per chain (128 t each)

// Scratch (device globals — no runtime allocation allowed).
__device__ float g_xw0[NELEM];
__device__ float g_xw1[NELEM];
__device__ float g_h0[NELEM];
__device__ float g_h1[NELEM];
__device__ float g_S2 [NCHAIN * NHC];  // per-half-chunk sum (written by proj)
__device__ float g_hl2[NCHAIN * NHC];  // per-half-chunk local-scan end value

// Deduped B' image for the MMA MLP: 128 rows x [Whi(128)|Wlo(128)] bf16,
// pitch 264 elems (528 B)
constexpr int BPITCHE = 264;
__device__ uint32_t g_Bimg[128 * BPITCHE / 2];   // 67584 bytes

// B' image for the MMA projection: 128 rows x 104 bf16 (pitch 208 B),
// K = [Whi(32) | Wlo(32) | Whi(32)]
constexpr int PPITCHE = 104;
__device__ uint32_t g_BimgP[128 * PPITCHE / 2];
__device__ float    g_biasP[128];

typedef unsigned long long u64;

__device__ __forceinline__ bool row_is_identity(const float* W, int j) {
    bool ok = true;
#pragma unroll
    for (int k = 0; k < HH; k++) ok &= (W[j * HH + k] == ((k == j) ? 1.0f : 0.0f));
    return ok;
}

__device__ __forceinline__ uint32_t smem_u32(const void* p) {
    uint32_t a;
    asm("{ .reg .u64 t; cvta.to.shared.u64 t, %1; cvt.u32.u64 %0, t; }"
        : "=r"(a) : "l"(p));
    return a;
}

// ============================================================================
// Prep: build both B' images + proj bias vector.
// ============================================================================
__global__ __launch_bounds__(512) void prep_kernel(
    const float* __restrict__ ff0w,
    const float* __restrict__ Wihf, const float* __restrict__ Wihb,
    const float* __restrict__ bihf, const float* __restrict__ bhhf,
    const float* __restrict__ bihb, const float* __restrict__ bhhb)
{
    const int tx = threadIdx.x;
    const int j  = tx >> 2;
    const int kq = tx & 3;

    // MLP image (deduped): [128 j][256 k], pitch 264; K = [Whi | Wlo]
    for (int kp = kq * 32; kp < (kq + 1) * 32; kp++) {
        const int c = 2 * kp;
        const int lo_type = (c >= 128);
        const int sk = lo_type ? (c - 128) : c;
        float w0 = ff0w[j * 128 + sk], w1 = ff0w[j * 128 + sk + 1];
        __nv_bfloat16 h0 = __float2bfloat16(w0), h1 = __float2bfloat16(w1);
        __nv_bfloat16 o0, o1;
        if (lo_type) {
            o0 = __float2bfloat16(w0 - __bfloat162float(h0));
            o1 = __float2bfloat16(w1 - __bfloat162float(h1));
        } else { o0 = h0; o1 = h1; }
        __nv_bfloat162 p2 = make_bfloat162(o0, o1);
        g_Bimg[j * (BPITCHE / 2) + kp] = *reinterpret_cast<uint32_t*>(&p2);
    }

    // proj image: [128 n][96 k], pitch 104; K = [Whi|Wlo|Whi]; n = dir*64+jr
    {
        const int n = j;
        const int dir = n >> 6, jr = n & 63;
        const float* W = dir ? Wihb : Wihf;
        for (int kp = kq * 12; kp < (kq + 1) * 12; kp++) {
            const int c = 2 * kp;
            int sk, lo_type;
            if (c < 32)      { sk = c;      lo_type = 0; }
            else if (c < 64) { sk = c - 32; lo_type = 1; }
            else             { sk = c - 64; lo_type = 0; }
            float w0 = W[jr * II + sk], w1 = W[jr * II + sk + 1];
            __nv_bfloat16 h0 = __float2bfloat16(w0), h1 = __float2bfloat16(w1);
            __nv_bfloat16 o0, o1;
            if (lo_type) {
                o0 = __float2bfloat16(w0 - __bfloat162float(h0));
                o1 = __float2bfloat16(w1 - __bfloat162float(h1));
            } else { o0 = h0; o1 = h1; }
            __nv_bfloat162 p2 = make_bfloat162(o0, o1);
            g_BimgP[n * (PPITCHE / 2) + kp] = *reinterpret_cast<uint32_t*>(&p2);
        }
        if (kq == 0)
            g_biasP[n] = dir ? (bihb[jr] + bhhb[jr]) : (bihf[jr] + bhhf[jr]);
    }
}

// ============================================================================
// Kernel 1: input projection via mma.sync (R13/R15 measured-best body) plus
// the R10-validated per-half-chunk stat walk (2x64 segments composed).
// ============================================================================
constexpr int PAPITCH = 208;
constexpr int PSM_A   = 0;
constexpr int PSM_B   = 128 * PAPITCH;              // 26624
constexpr int PSM_AB  = PSM_B + 128 * PAPITCH;      // 53248
constexpr int PSM_OUT = 128 * 132 * 4;              // 67584
constexpr int PSM_TOT = PSM_OUT > PSM_AB ? PSM_OUT : PSM_AB;

__global__ __launch_bounds__(256, 2)
void proj_mma_kernel(const float* __restrict__ x)
{
    extern __shared__ __align__(128) char smem[];
    __shared__ float sbias[128];
    __shared__ float2 sStat[2][128];

    const int tx   = threadIdx.x;
    const int wid  = tx >> 5;
    const int lane = tx & 31;
    const int row0 = blockIdx.x * 128;
    const int b    = row0 >> 11;            // TT = 2048
    const int t0   = row0 & (TT - 1);

    if (tx < 128) sbias[tx] = g_biasP[tx];

    {
        const float4* src = reinterpret_cast<const float4*>(g_BimgP);
        float4* dst = reinterpret_cast<float4*>(smem + PSM_B);
        for (int i = tx; i < PSM_B / 16; i += 256) dst[i] = src[i];
    }

    {
        const int r = tx >> 1, half = tx & 1;
        const float* px = &x[(size_t)(b * TT + t0 + r) * II];
        float hv[II];
#pragma unroll
        for (int q = 0; q < 8; q++) *(float4*)&hv[q * 4] = *(const float4*)&px[q * 4];
        char* A = smem + PSM_A + r * PAPITCH;
        if (half == 0) {
#pragma unroll
            for (int kq = 0; kq < 8; kq++) {
                const int c = kq * 4;
                __nv_bfloat162 q0 = make_bfloat162(__float2bfloat16(hv[c]),
                                                   __float2bfloat16(hv[c + 1]));
                __nv_bfloat162 q1 = make_bfloat162(__float2bfloat16(hv[c + 2]),
                                                   __float2bfloat16(hv[c + 3]));
                u64 pq = ((u64)(*reinterpret_cast<uint32_t*>(&q1)) << 32)
                       |  (u64)(*reinterpret_cast<uint32_t*>(&q0));
                *(u64*)(A + c * 2) = pq;
            }
        } else {
#pragma unroll
            for (int kq = 0; kq < 8; kq++) {
                const int c = kq * 4;
                __nv_bfloat16 b0 = __float2bfloat16(hv[c]);
                __nv_bfloat16 b1 = __float2bfloat16(hv[c + 1]);
                __nv_bfloat16 b2 = __float2bfloat16(hv[c + 2]);
                __nv_bfloat16 b3 = __float2bfloat16(hv[c + 3]);
                __nv_bfloat162 h01 = make_bfloat162(b0, b1);
                __nv_bfloat162 h23 = make_bfloat162(b2, b3);
                u64 hq = ((u64)(*reinterpret_cast<uint32_t*>(&h23)) << 32)
                       |  (u64)(*reinterpret_cast<uint32_t*>(&h01));
                __nv_bfloat162 l01 = make_bfloat162(
                    __float2bfloat16(hv[c]     - __bfloat162float(b0)),
                    __float2bfloat16(hv[c + 1] - __bfloat162float(b1)));
                __nv_bfloat162 l23 = make_bfloat162(
                    __float2bfloat16(hv[c + 2] - __bfloat162float(b2)),
                    __float2bfloat16(hv[c + 3] - __bfloat162float(b3)));
                u64 lq = ((u64)(*reinterpret_cast<uint32_t*>(&l23)) << 32)
                       |  (u64)(*reinterpret_cast<uint32_t*>(&l01));
                *(u64*)(A + (c + 32) * 2) = hq;
                *(u64*)(A + (c + 64) * 2) = lq;
            }
        }
    }
    __syncthreads();

    const uint32_t aAddr = smem_u32(smem) + PSM_A
        + (uint32_t)(wid * 16 + (lane & 15)) * PAPITCH + (uint32_t)(lane >> 4) * 16;
    const uint32_t bAddr = smem_u32(smem) + PSM_B
        + (uint32_t)(lane & 7) * PAPITCH + (uint32_t)((lane >> 3) & 1) * 16;

    float c[16][4];
#pragma unroll
    for (int nt = 0; nt < 16; nt++)
#pragma unroll
        for (int q = 0; q < 4; q++) c[nt][q] = 0.0f;

#pragma unroll
    for (int kk = 0; kk < 6; kk++) {
        uint32_t a0, a1, a2, a3;
        asm volatile("ldmatrix.sync.aligned.m8n8.x4.shared.b16 {%0,%1,%2,%3}, [%4];"
                     : "=r"(a0), "=r"(a1), "=r"(a2), "=r"(a3)
                     : "r"(aAddr + kk * 32));
#pragma unroll
        for (int nt = 0; nt < 16; nt++) {
            uint32_t b0, b1;
            asm volatile("ldmatrix.sync.aligned.m8n8.x2.shared.b16 {%0,%1}, [%2];"
                         : "=r"(b0), "=r"(b1)
                         : "r"(bAddr + (uint32_t)nt * 8 * PAPITCH + kk * 32));
            asm volatile(
                "mma.sync.aligned.m16n8k16.row.col.f32.bf16.bf16.f32 "
                "{%0,%1,%2,%3}, {%4,%5,%6,%7}, {%8,%9}, {%0,%1,%2,%3};"
                : "+f"(c[nt][0]), "+f"(c[nt][1]), "+f"(c[nt][2]), "+f"(c[nt][3])
                : "r"(a0), "r"(a1), "r"(a2), "r"(a3), "r"(b0), "r"(b1));
        }
    }
    __syncthreads();

    float* sout = reinterpret_cast<float*>(smem);
    {
        const int r0 = wid * 16 + (lane >> 2);
        const int r1 = r0 + 8;
#pragma unroll
        for (int nt = 0; nt < 16; nt++) {
            const int col = nt * 8 + (lane & 3) * 2;
            const float bb0 = sbias[col], bb1 = sbias[col + 1];
            sout[r0 * 132 + col]     = c[nt][0] + bb0;
            sout[r0 * 132 + col + 1] = c[nt][1] + bb1;
            sout[r1 * 132 + col]     = c[nt][2] + bb0;
            sout[r1 * 132 + col + 1] = c[nt][3] + bb1;
        }
    }
    __syncthreads();

    // coalesced store of raw xw
    for (int i = tx; i < 128 * 32; i += 256) {
        const int t = i >> 5, q = i & 31;
        float4 v = *(const float4*)&sout[t * 132 + q * 4];
        const int dir = q >> 4, j4 = (q & 15) * 4;
        float* plane = dir ? g_xw1 : g_xw0;
        *(float4*)&plane[(size_t)(b * TT + t0 + t) * HH + j4] = v;
    }

    // per-half-chunk scan stats: 2 segments per column, composed (max-plus)
    {
        const int col = tx & 127, seg = tx >> 7;
        const int dir = col >> 6;
        const int tstart = (dir == 0) ? seg * 64 : (127 - seg * 64);
        const int stp    = (dir == 0) ? 132 : -132;
        float S = 0.0f, h = 0.0f;
        int p = tstart * 132 + col;
#pragma unroll 8
        for (int i = 0; i < 64; i++) {
            float v = sout[p];
            S += v; h = fmaxf(v + h, 0.0f);
            p += stp;
        }
        sStat[seg][col] = make_float2(S, h);
    }
    __syncthreads();
    if (tx < 128) {
        const int col = tx, dir = col >> 6, j = col & 63;
        float2 s0 = sStat[0][col], s1 = sStat[1][col];
        const int hc = dir ? (15 - (t0 >> 7)) : (t0 >> 7);
        const int chain = b * 128 + dir * 64 + j;
        g_S2 [chain * NHC + hc] = s0.x + s1.x;
        g_hl2[chain * NHC + hc] = fmaxf(s1.x + s0.y, s1.y);
    }
}

// ============================================================================
// Fused scan (no phase-1 xw read): one block per (b, dir).
//   phase A: compose half-chunk stats -> chunk stats; 8-step boundary scan
//            into SMEM hin (64 threads).
//   phase B: per chunk, read xw once, recompute PS and h_local in registers
//            (bit-identical chain), write h = max(PS + hin, h_local).
//            chunk 0 has hin = 0 -> writes exactly h_local (monotonicity).
// General-W fallback unchanged (full serial matvec per block).
// ============================================================================
__global__ __launch_bounds__(128) void scan_fused(
    const float* __restrict__ Whhf, const float* __restrict__ Whhb)
{
    __shared__ float sHin[CHK][64];
    __shared__ int sOK;

    const int blk = blockIdx.x;          // 256 = b*2 + dir
    const int b = blk >> 1, dir = blk & 1;
    const int tx = threadIdx.x;
    const int jg = tx & 15, chunk = tx >> 4;
    const int j0 = jg * 4;
    const float* W = dir ? Whhb : Whhf;

    if (tx == 0) sOK = 1;
    __syncthreads();
    if (!row_is_identity(W, tx & 63)) atomicAnd(&sOK, 0);
    __syncthreads();

    const float* xw = dir ? g_xw1 : g_xw0;
    float*       hp = dir ? g_h1  : g_h0;

    if (sOK) {
        // phase A: boundary scan from half-chunk stats
        if (tx < 64) {
            const int chain = b * 128 + dir * 64 + tx;
            float hin = 0.0f;
#pragma unroll
            for (int c = 0; c < CHK; c++) {
                float S0 = g_S2 [chain * NHC + 2 * c];
                float h0 = g_hl2[chain * NHC + 2 * c];
                float S1 = g_S2 [chain * NHC + 2 * c + 1];
                float h1 = g_hl2[chain * NHC + 2 * c + 1];
                sHin[c][tx] = hin;
                const float S  = S0 + S1;
                const float hE = fmaxf(S1 + h0, h1);
                hin = fmaxf(S + hin, hE);
            }
        }
        __syncthreads();

        // phase B: single-pass h write
        const int tstart = dir ? (TT - 1 - chunk * CLEN) : chunk * CLEN;
        const ptrdiff_t step = dir ? -(ptrdiff_t)HH : (ptrdiff_t)HH;
        float4 hin = *(const float4*)&sHin[chunk][j0];
        const float* xp = xw + (size_t)(b * TT + tstart) * HH + j0;
        float*       hw = hp + (size_t)(b * TT + tstart) * HH + j0;
        float4 PS = make_float4(0.f, 0.f, 0.f, 0.f);
        float4 h  = make_float4(0.f, 0.f, 0.f, 0.f);
        for (int g = 0; g < CLEN / 8; g++) {
            float4 v[8];
#pragma unroll
            for (int u = 0; u < 8; u++) v[u] = *(const float4*)&xp[step * u];
#pragma unroll
            for (int u = 0; u < 8; u++) {
                PS.x += v[u].x; PS.y += v[u].y; PS.z += v[u].z; PS.w += v[u].w;
                h.x = fmaxf(v[u].x + h.x, 0.0f);
                h.y = fmaxf(v[u].y + h.y, 0.0f);
                h.z = fmaxf(v[u].z + h.z, 0.0f);
                h.w = fmaxf(v[u].w + h.w, 0.0f);
                float4 o;
                o.x = fmaxf(PS.x + hin.x, h.x);
                o.y = fmaxf(PS.y + hin.y, h.y);
                o.z = fmaxf(PS.z + hin.z, h.z);
                o.w = fmaxf(PS.w + hin.w, h.w);
                *(float4*)&hw[step * u] = o;
            }
            xp += step * 8; hw += step * 8;
        }
    } else {
        // general fallback: full serial matvec scan for this (b, dir)
        __shared__ float shv[HH];
        float wrow[HH];
        if (tx < HH) {
#pragma unroll
            for (int k = 0; k < HH; k++) wrow[k] = W[tx * HH + k];
            shv[tx] = 0.0f;
        }
        __syncthreads();
        for (int t = 0; t < TT; t++) {
            const int tt = dir ? (TT - 1 - t) : t;
            float acc = 0.0f;
            if (tx < HH) {
                acc = xw[(size_t)(b * TT + tt) * HH + tx];
#pragma unroll
                for (int k = 0; k < HH; k++) acc += wrow[k] * shv[k];
                acc = fmaxf(acc, 0.0f);
            }
            __syncthreads();
            if (tx < HH) {
                shv[tx] = acc;
                hp[(size_t)(b * TT + tt) * HH + tx] = acc;
            }
            __syncthreads();
        }
    }
}

// ============================================================================
// MLP head via warp-level mma.sync (R15 measured-best version, unchanged).
// ============================================================================
constexpr int APITCH = 528;
constexpr int SM_A   = 0;
constexpr int SM_B   = 128 * APITCH;           // 67584
constexpr int SM_TOT = SM_B + 128 * APITCH;    // 135168

__global__ __launch_bounds__(256, 1)
void mlp_mma_kernel(const float* __restrict__ ff0b,
                    const float* __restrict__ ff1w,
                    const float* __restrict__ ff1b,
                    float* __restrict__ out)
{
    extern __shared__ __align__(128) char smem[];
    __shared__ float sb0[128], sw1[128];

    const int tx   = threadIdx.x;
    const int wid  = tx >> 5;
    const int lane = tx & 31;
    const int row0 = blockIdx.x * 128;

    if (tx < 128) { sb0[tx] = ff0b[tx]; sw1[tx] = ff1w[tx]; }

    {
        const float4* src = reinterpret_cast<const float4*>(g_Bimg);
        float4* dst = reinterpret_cast<float4*>(smem + SM_B);
        for (int i = tx; i < SM_B / 16; i += 256) dst[i] = src[i];
    }

    {
        const int r = tx >> 1, half = tx & 1;
        const float* p0 = &g_h0[(size_t)(row0 + r) * HH];
        const float* p1 = &g_h1[(size_t)(row0 + r) * HH];
        float hv[128];
#pragma unroll
        for (int q = 0; q < 16; q++) *(float4*)&hv[q * 4]      = *(const float4*)&p0[q * 4];
#pragma unroll
        for (int q = 0; q < 16; q++) *(float4*)&hv[64 + q * 4] = *(const float4*)&p1[q * 4];
        char* A = smem + SM_A + r * APITCH;
        if (half == 0) {
#pragma unroll
            for (int kq = 0; kq < 32; kq++) {
                const int c = kq * 4;
                __nv_bfloat162 q0 = make_bfloat162(__float2bfloat16(hv[c]),
                                                   __float2bfloat16(hv[c + 1]));
                __nv_bfloat162 q1 = make_bfloat162(__float2bfloat16(hv[c + 2]),
                                                   __float2bfloat16(hv[c + 3]));
                u64 pq = ((u64)(*reinterpret_cast<uint32_t*>(&q1)) << 32)
                       |  (u64)(*reinterpret_cast<uint32_t*>(&q0));
                *(u64*)(A + c * 2) = pq;
            }
        } else {
#pragma unroll
            for (int kq = 0; kq < 32; kq++) {
                const int c = kq * 4;
                __nv_bfloat16 b0 = __float2bfloat16(hv[c]);
                __nv_bfloat16 b1 = __float2bfloat16(hv[c + 1]);
                __nv_bfloat16 b2 = __float2bfloat16(hv[c + 2]);
                __nv_bfloat16 b3 = __float2bfloat16(hv[c + 3]);
                __nv_bfloat162 l01 = make_bfloat162(
                    __float2bfloat16(hv[c]     - __bfloat162float(b0)),
                    __float2bfloat16(hv[c + 1] - __bfloat162float(b1)));
                __nv_bfloat162 l23 = make_bfloat162(
                    __float2bfloat16(hv[c + 2] - __bfloat162float(b2)),
                    __float2bfloat16(hv[c + 3] - __bfloat162float(b3)));
                u64 lq = ((u64)(*reinterpret_cast<uint32_t*>(&l23)) << 32)
                       |  (u64)(*reinterpret_cast<uint32_t*>(&l01));
                *(u64*)(A + 256 + c * 2) = lq;
            }
        }
    }
    __syncthreads();

    const uint32_t aAddr = smem_u32(smem) + SM_A
        + (uint32_t)(wid * 16 + (lane & 15)) * APITCH + (uint32_t)(lane >> 4) * 16;
    const uint32_t bAddr = smem_u32(smem) + SM_B
        + (uint32_t)((lane & 7) + ((lane >> 4) << 3)) * APITCH
        + (uint32_t)((lane >> 3) & 1) * 16;

    float c[16][4];
#pragma unroll
    for (int nt = 0; nt < 16; nt++)
#pragma unroll
        for (int q = 0; q < 4; q++) c[nt][q] = 0.0f;

#pragma unroll 1
    for (int kk = 0; kk < 24; kk++) {
        const uint32_t ao = (uint32_t)((kk < 8)  ? kk : (kk - 8))  * 32;
        const uint32_t bo = (uint32_t)((kk < 16) ? kk : (kk - 16)) * 32;
        uint32_t a0, a1, a2, a3;
        asm volatile("ldmatrix.sync.aligned.m8n8.x4.shared.b16 {%0,%1,%2,%3}, [%4];"
                     : "=r"(a0), "=r"(a1), "=r"(a2), "=r"(a3)
                     : "r"(aAddr + ao));
#pragma unroll
        for (int np = 0; np < 8; np++) {
            uint32_t b0, b1, b2, b3;
            asm volatile("ldmatrix.sync.aligned.m8n8.x4.shared.b16 {%0,%1,%2,%3}, [%4];"
                         : "=r"(b0), "=r"(b1), "=r"(b2), "=r"(b3)
                         : "r"(bAddr + (uint32_t)np * 16 * APITCH + bo));
            const int nt0 = np * 2, nt1 = nt0 + 1;
            asm volatile(
                "mma.sync.aligned.m16n8k16.row.col.f32.bf16.bf16.f32 "
                "{%0,%1,%2,%3}, {%4,%5,%6,%7}, {%8,%9}, {%0,%1,%2,%3};"
                : "+f"(c[nt0][0]), "+f"(c[nt0][1]), "+f"(c[nt0][2]), "+f"(c[nt0][3])
                : "r"(a0), "r"(a1), "r"(a2), "r"(a3), "r"(b0), "r"(b1));
            asm volatile(
                "mma.sync.aligned.m16n8k16.row.col.f32.bf16.bf16.f32 "
                "{%0,%1,%2,%3}, {%4,%5,%6,%7}, {%8,%9}, {%0,%1,%2,%3};"
                : "+f"(c[nt1][0]), "+f"(c[nt1][1]), "+f"(c[nt1][2]), "+f"(c[nt1][3])
                : "r"(a0), "r"(a1), "r"(a2), "r"(a3), "r"(b2), "r"(b3));
        }
    }

    float y0 = 0.0f, y1 = 0.0f;
#pragma unroll
    for (int nt = 0; nt < 16; nt++) {
        const int col = nt * 8 + (lane & 3) * 2;
        const float bb0 = sb0[col], bb1 = sb0[col + 1];
        const float ww0 = sw1[col], ww1 = sw1[col + 1];
        float z;
        z = c[nt][0] + bb0; y0 = fmaf(ww0, z > 0.0f ? z : 0.01f * z, y0);
        z = c[nt][1] + bb1; y0 = fmaf(ww1, z > 0.0f ? z : 0.01f * z, y0);
        z = c[nt][2] + bb0; y1 = fmaf(ww0, z > 0.0f ? z : 0.01f * z, y1);
        z = c[nt][3] + bb1; y1 = fmaf(ww1, z > 0.0f ? z : 0.01f * z, y1);
    }
    y0 += __shfl_xor_sync(0xffffffffu, y0, 1);
    y1 += __shfl_xor_sync(0xffffffffu, y1, 1);
    y0 += __shfl_xor_sync(0xffffffffu, y0, 2);
    y1 += __shfl_xor_sync(0xffffffffu, y1, 2);
    if ((lane & 3) == 0) {
        const float fb = ff1b[0];
        const int r = row0 + wid * 16 + (lane >> 2);
        out[r]     = y0 + fb;
        out[r + 8] = y1 + fb;
    }
}

// ============================================================================
extern "C" void kernel_launch(void* const* d_in, const int* in_sizes, int n_in,
                              void* d_out, int out_size)
{
    const float* x    = (const float*)d_in[0];
    const float* Wihf = (const float*)d_in[1];
    const float* Whhf = (const float*)d_in[2];
    const float* bihf = (const float*)d_in[3];
    const float* bhhf = (const float*)d_in[4];
    const float* Wihb = (const float*)d_in[5];
    const float* Whhb = (const float*)d_in[6];
    const float* bihb = (const float*)d_in[7];
    const float* bhhb = (const float*)d_in[8];
    const float* ff0w = (const float*)d_in[9];
    const float* ff0b = (const float*)d_in[10];
    const float* ff1w = (const float*)d_in[11];
    const float* ff1b = (const float*)d_in[12];

    cudaFuncSetAttribute(mlp_mma_kernel,
                         cudaFuncAttributeMaxDynamicSharedMemorySize, SM_TOT);
    cudaFuncSetAttribute(proj_mma_kernel,
                         cudaFuncAttributeMaxDynamicSharedMemorySize, PSM_TOT);

    prep_kernel<<<1, 512>>>(ff0w, Wihf, Wihb, bihf, bhhf, bihb, bhhb);
    proj_mma_kernel<<<2048, 256, PSM_TOT>>>(x);
    scan_fused<<<256, 128>>>(Whhf, Whhb);
    mlp_mma_kernel<<<2048, 256, SM_TOT>>>(ff0b, ff1w, ff1b, (float*)d_out);
}

// round 17
// speedup vs baseline: 1.3271x; 1.0320x over previous
#include <cuda_runtime.h>
#include <cuda_bf16.h>
#include <cstdint>
#include <cstddef>

// Problem constants (fixed by the reference)
#define BB 128
#define TT 2048
#define II 32
#define HH 64
constexpr int NROWS  = BB * TT;        // 262144
constexpr int NELEM  = NROWS * HH;     // 16,777,216 per plane
constexpr int NCHAIN = BB * 2 * HH;    // 16384 scan chains
constexpr int CHK    = 8;              // chunks per chain
constexpr int CLEN   = 256;            // chunk length
constexpr int NHC    = 16;             // half-chunks per chain (128 t each)

// Scratch (device globals — no runtime allocation allowed).
__device__ float g_xw0[NELEM];
__device__ float g_xw1[NELEM];
__device__ float g_h0[NELEM];
__device__ float g_h1[NELEM];
__device__ float g_S2 [NCHAIN * NHC];  // per-half-chunk sum (written by proj)
__device__ float g_hl2[NCHAIN * NHC];  // per-half-chunk local-scan end value

// Deduped B' image for the MMA MLP: 128 rows x [Whi(128)|Wlo(128)] bf16,
// pitch 264 elems (528 B)
constexpr int BPITCHE = 264;
__device__ uint32_t g_Bimg[128 * BPITCHE / 2];   // 67584 bytes

// B' image for the MMA projection: 128 rows x 104 bf16 (pitch 208 B),
// K = [Whi(32) | Wlo(32) | Whi(32)]
constexpr int PPITCHE = 104;
__device__ uint32_t g_BimgP[128 * PPITCHE / 2];
__device__ float    g_biasP[128];

typedef unsigned long long u64;

__device__ __forceinline__ bool row_is_identity(const float* W, int j) {
    bool ok = true;
#pragma unroll
    for (int k = 0; k < HH; k++) ok &= (W[j * HH + k] == ((k == j) ? 1.0f : 0.0f));
    return ok;
}

__device__ __forceinline__ uint32_t smem_u32(const void* p) {
    uint32_t a;
    asm("{ .reg .u64 t; cvta.to.shared.u64 t, %1; cvt.u32.u64 %0, t; }"
        : "=r"(a) : "l"(p));
    return a;
}

// ============================================================================
// Prep: build both B' images + proj bias vector.
// ============================================================================
__global__ __launch_bounds__(512) void prep_kernel(
    const float* __restrict__ ff0w,
    const float* __restrict__ Wihf, const float* __restrict__ Wihb,
    const float* __restrict__ bihf, const float* __restrict__ bhhf,
    const float* __restrict__ bihb, const float* __restrict__ bhhb)
{
    const int tx = threadIdx.x;
    const int j  = tx >> 2;
    const int kq = tx & 3;

    // MLP image (deduped): [128 j][256 k], pitch 264; K = [Whi | Wlo]
    for (int kp = kq * 32; kp < (kq + 1) * 32; kp++) {
        const int c = 2 * kp;
        const int lo_type = (c >= 128);
        const int sk = lo_type ? (c - 128) : c;
        float w0 = ff0w[j * 128 + sk], w1 = ff0w[j * 128 + sk + 1];
        __nv_bfloat16 h0 = __float2bfloat16(w0), h1 = __float2bfloat16(w1);
        __nv_bfloat16 o0, o1;
        if (lo_type) {
            o0 = __float2bfloat16(w0 - __bfloat162float(h0));
            o1 = __float2bfloat16(w1 - __bfloat162float(h1));
        } else { o0 = h0; o1 = h1; }
        __nv_bfloat162 p2 = make_bfloat162(o0, o1);
        g_Bimg[j * (BPITCHE / 2) + kp] = *reinterpret_cast<uint32_t*>(&p2);
    }

    // proj image: [128 n][96 k], pitch 104; K = [Whi|Wlo|Whi]; n = dir*64+jr
    {
        const int n = j;
        const int dir = n >> 6, jr = n & 63;
        const float* W = dir ? Wihb : Wihf;
        for (int kp = kq * 12; kp < (kq + 1) * 12; kp++) {
            const int c = 2 * kp;
            int sk, lo_type;
            if (c < 32)      { sk = c;      lo_type = 0; }
            else if (c < 64) { sk = c - 32; lo_type = 1; }
            else             { sk = c - 64; lo_type = 0; }
            float w0 = W[jr * II + sk], w1 = W[jr * II + sk + 1];
            __nv_bfloat16 h0 = __float2bfloat16(w0), h1 = __float2bfloat16(w1);
            __nv_bfloat16 o0, o1;
            if (lo_type) {
                o0 = __float2bfloat16(w0 - __bfloat162float(h0));
                o1 = __float2bfloat16(w1 - __bfloat162float(h1));
            } else { o0 = h0; o1 = h1; }
            __nv_bfloat162 p2 = make_bfloat162(o0, o1);
            g_BimgP[n * (PPITCHE / 2) + kp] = *reinterpret_cast<uint32_t*>(&p2);
        }
        if (kq == 0)
            g_biasP[n] = dir ? (bihb[jr] + bhhb[jr]) : (bihf[jr] + bhhf[jr]);
    }
}

// ============================================================================
// Kernel 1: input projection via mma.sync + per-half-chunk stats
// (R16 measured-best, unchanged).
// ============================================================================
constexpr int PAPITCH = 208;
constexpr int PSM_A   = 0;
constexpr int PSM_B   = 128 * PAPITCH;              // 26624
constexpr int PSM_AB  = PSM_B + 128 * PAPITCH;      // 53248
constexpr int PSM_OUT = 128 * 132 * 4;              // 67584
constexpr int PSM_TOT = PSM_OUT > PSM_AB ? PSM_OUT : PSM_AB;

__global__ __launch_bounds__(256, 2)
void proj_mma_kernel(const float* __restrict__ x)
{
    extern __shared__ __align__(128) char smem[];
    __shared__ float sbias[128];
    __shared__ float2 sStat[2][128];

    const int tx   = threadIdx.x;
    const int wid  = tx >> 5;
    const int lane = tx & 31;
    const int row0 = blockIdx.x * 128;
    const int b    = row0 >> 11;            // TT = 2048
    const int t0   = row0 & (TT - 1);

    if (tx < 128) sbias[tx] = g_biasP[tx];

    {
        const float4* src = reinterpret_cast<const float4*>(g_BimgP);
        float4* dst = reinterpret_cast<float4*>(smem + PSM_B);
        for (int i = tx; i < PSM_B / 16; i += 256) dst[i] = src[i];
    }

    {
        const int r = tx >> 1, half = tx & 1;
        const float* px = &x[(size_t)(b * TT + t0 + r) * II];
        float hv[II];
#pragma unroll
        for (int q = 0; q < 8; q++) *(float4*)&hv[q * 4] = *(const float4*)&px[q * 4];
        char* A = smem + PSM_A + r * PAPITCH;
        if (half == 0) {
#pragma unroll
            for (int kq = 0; kq < 8; kq++) {
                const int c = kq * 4;
                __nv_bfloat162 q0 = make_bfloat162(__float2bfloat16(hv[c]),
                                                   __float2bfloat16(hv[c + 1]));
                __nv_bfloat162 q1 = make_bfloat162(__float2bfloat16(hv[c + 2]),
                                                   __float2bfloat16(hv[c + 3]));
                u64 pq = ((u64)(*reinterpret_cast<uint32_t*>(&q1)) << 32)
                       |  (u64)(*reinterpret_cast<uint32_t*>(&q0));
                *(u64*)(A + c * 2) = pq;
            }
        } else {
#pragma unroll
            for (int kq = 0; kq < 8; kq++) {
                const int c = kq * 4;
                __nv_bfloat16 b0 = __float2bfloat16(hv[c]);
                __nv_bfloat16 b1 = __float2bfloat16(hv[c + 1]);
                __nv_bfloat16 b2 = __float2bfloat16(hv[c + 2]);
                __nv_bfloat16 b3 = __float2bfloat16(hv[c + 3]);
                __nv_bfloat162 h01 = make_bfloat162(b0, b1);
                __nv_bfloat162 h23 = make_bfloat162(b2, b3);
                u64 hq = ((u64)(*reinterpret_cast<uint32_t*>(&h23)) << 32)
                       |  (u64)(*reinterpret_cast<uint32_t*>(&h01));
                __nv_bfloat162 l01 = make_bfloat162(
                    __float2bfloat16(hv[c]     - __bfloat162float(b0)),
                    __float2bfloat16(hv[c + 1] - __bfloat162float(b1)));
                __nv_bfloat162 l23 = make_bfloat162(
                    __float2bfloat16(hv[c + 2] - __bfloat162float(b2)),
                    __float2bfloat16(hv[c + 3] - __bfloat162float(b3)));
                u64 lq = ((u64)(*reinterpret_cast<uint32_t*>(&l23)) << 32)
                       |  (u64)(*reinterpret_cast<uint32_t*>(&l01));
                *(u64*)(A + (c + 32) * 2) = hq;
                *(u64*)(A + (c + 64) * 2) = lq;
            }
        }
    }
    __syncthreads();

    const uint32_t aAddr = smem_u32(smem) + PSM_A
        + (uint32_t)(wid * 16 + (lane & 15)) * PAPITCH + (uint32_t)(lane >> 4) * 16;
    const uint32_t bAddr = smem_u32(smem) + PSM_B
        + (uint32_t)(lane & 7) * PAPITCH + (uint32_t)((lane >> 3) & 1) * 16;

    float c[16][4];
#pragma unroll
    for (int nt = 0; nt < 16; nt++)
#pragma unroll
        for (int q = 0; q < 4; q++) c[nt][q] = 0.0f;

#pragma unroll
    for (int kk = 0; kk < 6; kk++) {
        uint32_t a0, a1, a2, a3;
        asm volatile("ldmatrix.sync.aligned.m8n8.x4.shared.b16 {%0,%1,%2,%3}, [%4];"
                     : "=r"(a0), "=r"(a1), "=r"(a2), "=r"(a3)
                     : "r"(aAddr + kk * 32));
#pragma unroll
        for (int nt = 0; nt < 16; nt++) {
            uint32_t b0, b1;
            asm volatile("ldmatrix.sync.aligned.m8n8.x2.shared.b16 {%0,%1}, [%2];"
                         : "=r"(b0), "=r"(b1)
                         : "r"(bAddr + (uint32_t)nt * 8 * PAPITCH + kk * 32));
            asm volatile(
                "mma.sync.aligned.m16n8k16.row.col.f32.bf16.bf16.f32 "
                "{%0,%1,%2,%3}, {%4,%5,%6,%7}, {%8,%9}, {%0,%1,%2,%3};"
                : "+f"(c[nt][0]), "+f"(c[nt][1]), "+f"(c[nt][2]), "+f"(c[nt][3])
                : "r"(a0), "r"(a1), "r"(a2), "r"(a3), "r"(b0), "r"(b1));
        }
    }
    __syncthreads();

    float* sout = reinterpret_cast<float*>(smem);
    {
        const int r0 = wid * 16 + (lane >> 2);
        const int r1 = r0 + 8;
#pragma unroll
        for (int nt = 0; nt < 16; nt++) {
            const int col = nt * 8 + (lane & 3) * 2;
            const float bb0 = sbias[col], bb1 = sbias[col + 1];
            sout[r0 * 132 + col]     = c[nt][0] + bb0;
            sout[r0 * 132 + col + 1] = c[nt][1] + bb1;
            sout[r1 * 132 + col]     = c[nt][2] + bb0;
            sout[r1 * 132 + col + 1] = c[nt][3] + bb1;
        }
    }
    __syncthreads();

    // coalesced store of raw xw
    for (int i = tx; i < 128 * 32; i += 256) {
        const int t = i >> 5, q = i & 31;
        float4 v = *(const float4*)&sout[t * 132 + q * 4];
        const int dir = q >> 4, j4 = (q & 15) * 4;
        float* plane = dir ? g_xw1 : g_xw0;
        *(float4*)&plane[(size_t)(b * TT + t0 + t) * HH + j4] = v;
    }

    // per-half-chunk scan stats: 2 segments per column, composed (max-plus)
    {
        const int col = tx & 127, seg = tx >> 7;
        const int dir = col >> 6;
        const int tstart = (dir == 0) ? seg * 64 : (127 - seg * 64);
        const int stp    = (dir == 0) ? 132 : -132;
        float S = 0.0f, h = 0.0f;
        int p = tstart * 132 + col;
#pragma unroll 8
        for (int i = 0; i < 64; i++) {
            float v = sout[p];
            S += v; h = fmaxf(v + h, 0.0f);
            p += stp;
        }
        sStat[seg][col] = make_float2(S, h);
    }
    __syncthreads();
    if (tx < 128) {
        const int col = tx, dir = col >> 6, j = col & 63;
        float2 s0 = sStat[0][col], s1 = sStat[1][col];
        const int hc = dir ? (15 - (t0 >> 7)) : (t0 >> 7);
        const int chain = b * 128 + dir * 64 + j;
        g_S2 [chain * NHC + hc] = s0.x + s1.x;
        g_hl2[chain * NHC + hc] = fmaxf(s1.x + s0.y, s1.y);
    }
}

// ============================================================================
// Fused scan (R16 measured-best, unchanged).
// ============================================================================
__global__ __launch_bounds__(128) void scan_fused(
    const float* __restrict__ Whhf, const float* __restrict__ Whhb)
{
    __shared__ float sHin[CHK][64];
    __shared__ int sOK;

    const int blk = blockIdx.x;          // 256 = b*2 + dir
    const int b = blk >> 1, dir = blk & 1;
    const int tx = threadIdx.x;
    const int jg = tx & 15, chunk = tx >> 4;
    const int j0 = jg * 4;
    const float* W = dir ? Whhb : Whhf;

    if (tx == 0) sOK = 1;
    __syncthreads();
    if (!row_is_identity(W, tx & 63)) atomicAnd(&sOK, 0);
    __syncthreads();

    const float* xw = dir ? g_xw1 : g_xw0;
    float*       hp = dir ? g_h1  : g_h0;

    if (sOK) {
        if (tx < 64) {
            const int chain = b * 128 + dir * 64 + tx;
            float hin = 0.0f;
#pragma unroll
            for (int c = 0; c < CHK; c++) {
                float S0 = g_S2 [chain * NHC + 2 * c];
                float h0 = g_hl2[chain * NHC + 2 * c];
                float S1 = g_S2 [chain * NHC + 2 * c + 1];
                float h1 = g_hl2[chain * NHC + 2 * c + 1];
                sHin[c][tx] = hin;
                const float S  = S0 + S1;
                const float hE = fmaxf(S1 + h0, h1);
                hin = fmaxf(S + hin, hE);
            }
        }
        __syncthreads();

        const int tstart = dir ? (TT - 1 - chunk * CLEN) : chunk * CLEN;
        const ptrdiff_t step = dir ? -(ptrdiff_t)HH : (ptrdiff_t)HH;
        float4 hin = *(const float4*)&sHin[chunk][j0];
        const float* xp = xw + (size_t)(b * TT + tstart) * HH + j0;
        float*       hw = hp + (size_t)(b * TT + tstart) * HH + j0;
        float4 PS = make_float4(0.f, 0.f, 0.f, 0.f);
        float4 h  = make_float4(0.f, 0.f, 0.f, 0.f);
        for (int g = 0; g < CLEN / 8; g++) {
            float4 v[8];
#pragma unroll
            for (int u = 0; u < 8; u++) v[u] = *(const float4*)&xp[step * u];
#pragma unroll
            for (int u = 0; u < 8; u++) {
                PS.x += v[u].x; PS.y += v[u].y; PS.z += v[u].z; PS.w += v[u].w;
                h.x = fmaxf(v[u].x + h.x, 0.0f);
                h.y = fmaxf(v[u].y + h.y, 0.0f);
                h.z = fmaxf(v[u].z + h.z, 0.0f);
                h.w = fmaxf(v[u].w + h.w, 0.0f);
                float4 o;
                o.x = fmaxf(PS.x + hin.x, h.x);
                o.y = fmaxf(PS.y + hin.y, h.y);
                o.z = fmaxf(PS.z + hin.z, h.z);
                o.w = fmaxf(PS.w + hin.w, h.w);
                *(float4*)&hw[step * u] = o;
            }
            xp += step * 8; hw += step * 8;
        }
    } else {
        __shared__ float shv[HH];
        float wrow[HH];
        if (tx < HH) {
#pragma unroll
            for (int k = 0; k < HH; k++) wrow[k] = W[tx * HH + k];
            shv[tx] = 0.0f;
        }
        __syncthreads();
        for (int t = 0; t < TT; t++) {
            const int tt = dir ? (TT - 1 - t) : t;
            float acc = 0.0f;
            if (tx < HH) {
                acc = xw[(size_t)(b * TT + tt) * HH + tx];
#pragma unroll
                for (int k = 0; k < HH; k++) acc += wrow[k] * shv[k];
                acc = fmaxf(acc, 0.0f);
            }
            __syncthreads();
            if (tx < HH) {
                shv[tx] = acc;
                hp[(size_t)(b * TT + tt) * HH + tx] = acc;
            }
            __syncthreads();
        }
    }
}

// ============================================================================
// MLP head via warp-level mma.sync: 128-row tile, warps split over m AND n.
// 8 warps = 4 m-pairs (32 rows) x 2 n-halves (64 cols): B LDSM per warp
// halves (4 paired-x4/kk) at the cost of 2 A-x4/kk — CTA LDSM bytes -33%.
// Cross-half reduce via 1 KB static SMEM. A'-staging split into two 64-float
// plane passes to halve peak register live range.
// ============================================================================
constexpr int APITCH = 528;
constexpr int SM_A   = 0;
constexpr int SM_B   = 128 * APITCH;           // 67584
constexpr int SM_TOT = SM_B + 128 * APITCH;    // 135168

__global__ __launch_bounds__(256, 1)
void mlp_mma_kernel(const float* __restrict__ ff0b,
                    const float* __restrict__ ff1w,
                    const float* __restrict__ ff1b,
                    float* __restrict__ out)
{
    extern __shared__ __align__(128) char smem[];
    __shared__ float sb0[128], sw1[128];
    __shared__ float sPart[2][4][32];

    const int tx   = threadIdx.x;
    const int wid  = tx >> 5;
    const int lane = tx & 31;
    const int row0 = blockIdx.x * 128;
    const int mp   = wid & 3;            // m-pair (rows mp*32 .. mp*32+31)
    const int nh   = wid >> 2;           // n-half (cols nh*64 .. nh*64+63)

    if (tx < 128) { sb0[tx] = ff0b[tx]; sw1[tx] = ff1w[tx]; }

    // copy B' image: 4224 float4
    {
        const float4* src = reinterpret_cast<const float4*>(g_Bimg);
        float4* dst = reinterpret_cast<float4*>(smem + SM_B);
        for (int i = tx; i < SM_B / 16; i += 256) dst[i] = src[i];
    }

    // build deduped A' = [Hhi | Hlo] from h planes (two 64-float passes)
    {
        const int r = tx >> 1, half = tx & 1;
        char* A = smem + SM_A + r * APITCH;
#pragma unroll
        for (int pl = 0; pl < 2; pl++) {
            const float* hp = (pl ? g_h1 : g_h0) + (size_t)(row0 + r) * HH;
            float hv[64];
#pragma unroll
            for (int q = 0; q < 16; q++) *(float4*)&hv[q * 4] = *(const float4*)&hp[q * 4];
            if (half == 0) {
                // Hhi block: bytes [0, 256); plane pl -> cols pl*64..
#pragma unroll
                for (int kq = 0; kq < 16; kq++) {
                    const int c = kq * 4;
                    __nv_bfloat162 q0 = make_bfloat162(__float2bfloat16(hv[c]),
                                                       __float2bfloat16(hv[c + 1]));
                    __nv_bfloat162 q1 = make_bfloat162(__float2bfloat16(hv[c + 2]),
                                                       __float2bfloat16(hv[c + 3]));
                    u64 pq = ((u64)(*reinterpret_cast<uint32_t*>(&q1)) << 32)
                           |  (u64)(*reinterpret_cast<uint32_t*>(&q0));
                    *(u64*)(A + pl * 128 + c * 2) = pq;
                }
            } else {
                // Hlo block: bytes [256, 512)
#pragma unroll
                for (int kq = 0; kq < 16; kq++) {
                    const int c = kq * 4;
                    __nv_bfloat16 b0 = __float2bfloat16(hv[c]);
                    __nv_bfloat16 b1 = __float2bfloat16(hv[c + 1]);
                    __nv_bfloat16 b2 = __float2bfloat16(hv[c + 2]);
                    __nv_bfloat16 b3 = __float2bfloat16(hv[c + 3]);
                    __nv_bfloat162 l01 = make_bfloat162(
                        __float2bfloat16(hv[c]     - __bfloat162float(b0)),
                        __float2bfloat16(hv[c + 1] - __bfloat162float(b1)));
                    __nv_bfloat162 l23 = make_bfloat162(
                        __float2bfloat16(hv[c + 2] - __bfloat162float(b2)),
                        __float2bfloat16(hv[c + 3] - __bfloat162float(b3)));
                    u64 lq = ((u64)(*reinterpret_cast<uint32_t*>(&l23)) << 32)
                           |  (u64)(*reinterpret_cast<uint32_t*>(&l01));
                    *(u64*)(A + 256 + pl * 128 + c * 2) = lq;
                }
            }
        }
    }
    __syncthreads();

    // mainloop: warp = (m-pair mp) x (n-half nh)
    const uint32_t aAddr0 = smem_u32(smem) + SM_A
        + (uint32_t)(mp * 32 + (lane & 15)) * APITCH + (uint32_t)(lane >> 4) * 16;
    const uint32_t aAddr1 = aAddr0 + 16u * APITCH;
    const uint32_t bAddr = smem_u32(smem) + SM_B
        + (uint32_t)(nh * 64 + (lane & 7) + ((lane >> 4) << 3)) * APITCH
        + (uint32_t)((lane >> 3) & 1) * 16;

    float c[16][4];   // [0..7]: m-tile mp*2, nt 0..7; [8..15]: m-tile mp*2+1
#pragma unroll
    for (int nt = 0; nt < 16; nt++)
#pragma unroll
        for (int q = 0; q < 4; q++) c[nt][q] = 0.0f;

#pragma unroll 1
    for (int kk = 0; kk < 24; kk++) {
        const uint32_t ao = (uint32_t)((kk < 8)  ? kk : (kk - 8))  * 32;
        const uint32_t bo = (uint32_t)((kk < 16) ? kk : (kk - 16)) * 32;
        uint32_t a0, a1, a2, a3, a4, a5, a6, a7;
        asm volatile("ldmatrix.sync.aligned.m8n8.x4.shared.b16 {%0,%1,%2,%3}, [%4];"
                     : "=r"(a0), "=r"(a1), "=r"(a2), "=r"(a3)
                     : "r"(aAddr0 + ao));
        asm volatile("ldmatrix.sync.aligned.m8n8.x4.shared.b16 {%0,%1,%2,%3}, [%4];"
                     : "=r"(a4), "=r"(a5), "=r"(a6), "=r"(a7)
                     : "r"(aAddr1 + ao));
#pragma unroll
        for (int np = 0; np < 4; np++) {
            uint32_t b0, b1, b2, b3;
            asm volatile("ldmatrix.sync.aligned.m8n8.x4.shared.b16 {%0,%1,%2,%3}, [%4];"
                         : "=r"(b0), "=r"(b1), "=r"(b2), "=r"(b3)
                         : "r"(bAddr + (uint32_t)np * 16 * APITCH + bo));
            const int nt0 = np * 2, nt1 = nt0 + 1;
            asm volatile(
                "mma.sync.aligned.m16n8k16.row.col.f32.bf16.bf16.f32 "
                "{%0,%1,%2,%3}, {%4,%5,%6,%7}, {%8,%9}, {%0,%1,%2,%3};"
                : "+f"(c[nt0][0]), "+f"(c[nt0][1]), "+f"(c[nt0][2]), "+f"(c[nt0][3])
                : "r"(a0), "r"(a1), "r"(a2), "r"(a3), "r"(b0), "r"(b1));
            asm volatile(
                "mma.sync.aligned.m16n8k16.row.col.f32.bf16.bf16.f32 "
                "{%0,%1,%2,%3}, {%4,%5,%6,%7}, {%8,%9}, {%0,%1,%2,%3};"
                : "+f"(c[nt1][0]), "+f"(c[nt1][1]), "+f"(c[nt1][2]), "+f"(c[nt1][3])
                : "r"(a0), "r"(a1), "r"(a2), "r"(a3), "r"(b2), "r"(b3));
            asm volatile(
                "mma.sync.aligned.m16n8k16.row.col.f32.bf16.bf16.f32 "
                "{%0,%1,%2,%3}, {%4,%5,%6,%7}, {%8,%9}, {%0,%1,%2,%3};"
                : "+f"(c[8 + nt0][0]), "+f"(c[8 + nt0][1]), "+f"(c[8 + nt0][2]), "+f"(c[8 + nt0][3])
                : "r"(a4), "r"(a5), "r"(a6), "r"(a7), "r"(b0), "r"(b1));
            asm volatile(
                "mma.sync.aligned.m16n8k16.row.col.f32.bf16.bf16.f32 "
                "{%0,%1,%2,%3}, {%4,%5,%6,%7}, {%8,%9}, {%0,%1,%2,%3};"
                : "+f"(c[8 + nt1][0]), "+f"(c[8 + nt1][1]), "+f"(c[8 + nt1][2]), "+f"(c[8 + nt1][3])
                : "r"(a4), "r"(a5), "r"(a6), "r"(a7), "r"(b2), "r"(b3));
        }
    }

    // epilogue: per-warp partial over its n-half, both m-tiles
#pragma unroll
    for (int mtl = 0; mtl < 2; mtl++) {
        float y0 = 0.0f, y1 = 0.0f;
#pragma unroll
        for (int nt = 0; nt < 8; nt++) {
            const int col = nh * 64 + nt * 8 + (lane & 3) * 2;
            const float bb0 = sb0[col], bb1 = sb0[col + 1];
            const float ww0 = sw1[col], ww1 = sw1[col + 1];
            const float* cc = c[mtl * 8 + nt];
            float z;
            z = cc[0] + bb0; y0 = fmaf(ww0, z > 0.0f ? z : 0.01f * z, y0);
            z = cc[1] + bb1; y0 = fmaf(ww1, z > 0.0f ? z : 0.01f * z, y0);
            z = cc[2] + bb0; y1 = fmaf(ww0, z > 0.0f ? z : 0.01f * z, y1);
            z = cc[3] + bb1; y1 = fmaf(ww1, z > 0.0f ? z : 0.01f * z, y1);
        }
        y0 += __shfl_xor_sync(0xffffffffu, y0, 1);
        y1 += __shfl_xor_sync(0xffffffffu, y1, 1);
        y0 += __shfl_xor_sync(0xffffffffu, y0, 2);
        y1 += __shfl_xor_sync(0xffffffffu, y1, 2);
        if ((lane & 3) == 0) {
            const int r = lane >> 2;            // 0..7
            sPart[nh][mp][mtl * 16 + r]     = y0;
            sPart[nh][mp][mtl * 16 + r + 8] = y1;
        }
    }
    __syncthreads();
    if (tx < 128) {
        const int mp2 = tx >> 5, idx = tx & 31;
        out[row0 + mp2 * 32 + idx] =
            sPart[0][mp2][idx] + sPart[1][mp2][idx] + ff1b[0];
    }
}

// ============================================================================
extern "C" void kernel_launch(void* const* d_in, const int* in_sizes, int n_in,
                              void* d_out, int out_size)
{
    const float* x    = (const float*)d_in[0];
    const float* Wihf = (const float*)d_in[1];
    const float* Whhf = (const float*)d_in[2];
    const float* bihf = (const float*)d_in[3];
    const float* bhhf = (const float*)d_in[4];
    const float* Wihb = (const float*)d_in[5];
    const float* Whhb = (const float*)d_in[6];
    const float* bihb = (const float*)d_in[7];
    const float* bhhb = (const float*)d_in[8];
    const float* ff0w = (const float*)d_in[9];
    const float* ff0b = (const float*)d_in[10];
    const float* ff1w = (const float*)d_in[11];
    const float* ff1b = (const float*)d_in[12];

    cudaFuncSetAttribute(mlp_mma_kernel,
                         cudaFuncAttributeMaxDynamicSharedMemorySize, SM_TOT);
    cudaFuncSetAttribute(proj_mma_kernel,
                         cudaFuncAttributeMaxDynamicSharedMemorySize, PSM_TOT);

    prep_kernel<<<1, 512>>>(ff0w, Wihf, Wihb, bihf, bhhf, bihb, bhhb);
    proj_mma_kernel<<<2048, 256, PSM_TOT>>>(x);
    scan_fused<<<256, 128>>>(Whhf, Whhb);
    mlp_mma_kernel<<<2048, 256, SM_TOT>>>(ff0b, ff1w, ff1b, (float*)d_out);
}